// round 12
// baseline (speedup 1.0000x reference)
#include <cuda_runtime.h>
#include <cuda_fp16.h>
#include <cstdint>

#define B_DIM   8192
#define IN_DIM  4096
#define OUT_DIM 4096

// ---------------- scratch (static device globals: allocation-free) ----------
// Tiled layout: 16KB blocks = (256 rows x 32 cols) of halves, 64B rows, SW64.
// block index = (row>>8)*KBLK + (col>>5); within: SWZ64((row&255)*64 + (col&31)*2)
// rows 0-127 of a block = first 8KB, rows 128-255 = second 8KB.
__device__ __align__(1024) __half g_xh[(size_t)B_DIM * IN_DIM];     // 64 MB
__device__ __align__(1024) __half g_wh[(size_t)OUT_DIM * IN_DIM];   // 32 MB
__device__ float g_bias[OUT_DIM];
__device__ float g_partial[1024];

// ---------------- common helpers --------------------------------------------
__device__ __forceinline__ uint32_t smem_u32(const void* p) {
    return (uint32_t)__cvta_generic_to_shared(p);
}
#define SWZ64(o) ((o) ^ (((o) >> 3) & 0x30))

// ---------------- GEMM tiling ------------------------------------------------
// Persistent: 148 CTAs as 74 clusters of 2. cg2 pair computes a 256(M)x512(N)
// tile as two N=256 atoms (D cols 0-255 / 256-511). Per-CTA per TK=32 kstep:
// A own 128 rows (8KB) + B own 256-row band (16KB). 9-stage ring of 24KB.
#define STAGES 9
#define TK 32
#define KSTEPS (IN_DIM / TK)            // 128
#define A_ST 8192                       // A half: 128 rows * 64B
#define B_ST 16384                      // B band: 256 rows * 64B
#define STAGE_BYTES (A_ST + B_ST)       // 24576
#define TILE_BYTES 16384                // one gmem conv block (256 rows x 32 cols)
#define KBLK (IN_DIM / TK)              // 128 k-blocks per 256-row band
#define NUM_MT 32                       // m tiles of 256
#define NUM_NT 8                        // n tiles of 512
#define NUM_PT (NUM_MT * NUM_NT)        // 256 pair-tiles
#define NUM_CLUSTERS 74
#define SM_TMEMPTR 0
#define SM_FULL 16
#define SM_EMPTY (SM_FULL + STAGES * 8)          // 88
#define SM_PEERFULL (SM_EMPTY + STAGES * 8)      // 160
#define SM_DONE (SM_PEERFULL + STAGES * 8)       // 232
#define SM_TFREE (SM_DONE + 8)                   // 240 (single slot)
#define SM_DATA 1024
#define GEMM_SMEM (SM_DATA + STAGES * STAGE_BYTES)  // 222208 (<= 232448 opt-in)
#define GEMM_THREADS 320   // warps 0-7 epilogue, warp 8 MMA(rank0)/fwd(rank1), warp 9 producer

// ============================================================================
// Arch-feature-gated tcgen05/cluster helpers (only for sm_10Xa targets)
// ============================================================================
#if defined(__CUDA_ARCH_FEAT_SM103_ALL) || defined(__CUDA_ARCH_FEAT_SM100_ALL) || defined(__CUDA_ARCH_FEAT_SM110_ALL)
#define HAS_TCGEN05 1

__device__ __forceinline__ uint32_t elect_one_pred() {
    uint32_t pred;
    asm volatile("{\n\t.reg .pred p;\n\telect.sync _|p, 0xFFFFFFFF;\n\t"
                 "selp.b32 %0, 1, 0, p;\n\t}" : "=r"(pred));
    return pred;
}
__device__ __forceinline__ uint32_t cluster_rank() {
    uint32_t r;
    asm("mov.u32 %0, %%cluster_ctarank;" : "=r"(r));
    return r;
}
#define CLUSTER_SYNC() do { \
    asm volatile("barrier.cluster.arrive.aligned;" ::: "memory"); \
    asm volatile("barrier.cluster.wait.aligned;" ::: "memory"); \
} while (0)

#define MBARRIER_INIT(addr, count) \
    asm volatile("mbarrier.init.shared.b64 [%0], %1;" :: "r"((uint32_t)(addr)), "r"((uint32_t)(count)) : "memory")
#define MBARRIER_ARRIVE(addr) \
    asm volatile("mbarrier.arrive.shared.b64 _, [%0];" :: "r"((uint32_t)(addr)) : "memory")
#define MBARRIER_ARRIVE_CLUSTER(local_addr, target_rank) \
    asm volatile("{\n\t.reg .b32 remAddr;\n\t" \
        "mapa.shared::cluster.u32 remAddr, %0, %1;\n\t" \
        "mbarrier.arrive.shared::cluster.b64 _, [remAddr];\n\t}" \
        :: "r"((uint32_t)(local_addr)), "r"((uint32_t)(target_rank)) : "memory")
#define MBARRIER_EXPECT_TX(addr, bytes) \
    asm volatile("mbarrier.arrive.expect_tx.shared.b64 _, [%0], %1;" :: "r"((uint32_t)(addr)), "r"((uint32_t)(bytes)) : "memory")
#define MBARRIER_WAIT_PARITY(mbar_smem_addr, phase_parity) do { \
    uint32_t _mbar = (uint32_t)(mbar_smem_addr); \
    uint32_t _parity = (uint32_t)(phase_parity); \
    uint32_t _done; \
    asm volatile("{\n\t.reg .pred p;\n\t" \
        "mbarrier.try_wait.parity.acquire.cta.shared::cta.b64 p, [%1], %2;\n\t" \
        "selp.b32 %0, 1, 0, p;\n\t}" : "=r"(_done) : "r"(_mbar), "r"(_parity) : "memory"); \
    if (!_done) { \
        asm volatile("{\n\t.reg .pred P1;\n\t" \
            "WAIT_LOOP_%=:\n\t" \
            "mbarrier.try_wait.parity.acquire.cta.shared::cta.b64 P1, [%0], %1, 0x989680;\n\t" \
            "@P1 bra.uni WAIT_DONE_%=;\n\t" \
            "bra.uni WAIT_LOOP_%=;\n\t" \
            "WAIT_DONE_%=:\n\t}" :: "r"(_mbar), "r"(_parity) : "memory"); \
    } \
} while (0)

#define BULK_G2S(dst, src, bytes, mbar) \
    asm volatile("cp.async.bulk.shared::cta.global.mbarrier::complete_tx::bytes [%0], [%1], %2, [%3];" \
        :: "r"((uint32_t)(dst)), "l"(src), "r"((uint32_t)(bytes)), "r"((uint32_t)(mbar)) : "memory")

#define TCGEN05_ALLOC_CG2(smem_result_addr, nCols) \
    asm volatile("tcgen05.alloc.cta_group::2.sync.aligned.shared::cta.b32 [%0], %1;" \
        :: "r"((uint32_t)(smem_result_addr)), "r"((uint32_t)(nCols)) : "memory")
#define TCGEN05_DEALLOC_CG2(tmem_addr, nCols) \
    asm volatile("tcgen05.dealloc.cta_group::2.sync.aligned.b32 %0, %1;" :: "r"(tmem_addr), "r"((uint32_t)(nCols)))
#define TCGEN05_RELINQUISH_CG2() \
    asm volatile("tcgen05.relinquish_alloc_permit.cta_group::2.sync.aligned;")
#define TCGEN05_COMMIT_MC_CG2(mbar, mask) \
    asm volatile("tcgen05.commit.cta_group::2.mbarrier::arrive::one.shared::cluster.multicast::cluster.b64 [%0], %1;" \
        :: "r"((uint32_t)(mbar)), "h"((uint16_t)(mask)) : "memory")
#define TCGEN05_FENCE_AFTER()  asm volatile("tcgen05.fence::after_thread_sync;" ::: "memory")
#define TCGEN05_FENCE_BEFORE() asm volatile("tcgen05.fence::before_thread_sync;" ::: "memory")
#define TCGEN05_WAIT_LD()      asm volatile("tcgen05.wait::ld.sync.aligned;" ::: "memory")
#define FENCE_PROXY_ASYNC()    asm volatile("fence.proxy.async.shared::cta;" ::: "memory")

#define TCGEN05_LD_32X32B_X32(r, tmem_addr) \
    asm volatile("tcgen05.ld.sync.aligned.32x32b.x32.b32 " \
        "{%0, %1, %2, %3, %4, %5, %6, %7, " \
        " %8, %9, %10, %11, %12, %13, %14, %15, " \
        " %16, %17, %18, %19, %20, %21, %22, %23, " \
        " %24, %25, %26, %27, %28, %29, %30, %31}, [%32];" \
        : "=r"((r)[0]),  "=r"((r)[1]),  "=r"((r)[2]),  "=r"((r)[3]), \
          "=r"((r)[4]),  "=r"((r)[5]),  "=r"((r)[6]),  "=r"((r)[7]), \
          "=r"((r)[8]),  "=r"((r)[9]),  "=r"((r)[10]), "=r"((r)[11]), \
          "=r"((r)[12]), "=r"((r)[13]), "=r"((r)[14]), "=r"((r)[15]), \
          "=r"((r)[16]), "=r"((r)[17]), "=r"((r)[18]), "=r"((r)[19]), \
          "=r"((r)[20]), "=r"((r)[21]), "=r"((r)[22]), "=r"((r)[23]), \
          "=r"((r)[24]), "=r"((r)[25]), "=r"((r)[26]), "=r"((r)[27]), \
          "=r"((r)[28]), "=r"((r)[29]), "=r"((r)[30]), "=r"((r)[31]) \
        : "r"(tmem_addr))

// cg2 f16 SS MMA: M=256 across the pair, 8 disable-lane regs (all zero).
__device__ __forceinline__ void mma_f16_ss_cg2(uint32_t d, uint64_t a_desc, uint64_t b_desc,
                                               uint32_t idesc, uint32_t enable) {
    asm volatile("{\n\t.reg .pred p;\n\tsetp.ne.u32 p, %5, 0;\n\t"
        "tcgen05.mma.cta_group::2.kind::f16 [%0], %1, %2, %3, "
        "{%4, %4, %4, %4, %4, %4, %4, %4}, p;\n\t}"
        :: "r"(d), "l"(a_desc), "l"(b_desc), "r"(idesc), "r"(0u), "r"(enable) : "memory");
}
// SW64 K-major descriptor: layout=4, version=1, SBO=32 (512B per 8-row atom), LBO=1
__device__ __forceinline__ uint64_t make_desc64(uint32_t addr) {
    const uint64_t base = (4ULL << 61) | (1ULL << 46) | (32ULL << 32) | (1ULL << 16);
    return base | ((uint64_t)(addr >> 4) & 0x3FFF);
}
// F32 acc (1<<4), f16 inputs, N=256 (bits[17:22]=N>>3), M=256 (bits[24:28]=M>>4)
#define IDESC_CG2 ((1u << 4) | (32u << 17) | (16u << 24))
#endif  // arch feature

// ---------------- kernel 1: fused conversions --------------------------------
// blocks 0-1023:    W -> fp16 tiled SW64 + KL partials (16384 elems/block)
// blocks 1024-3071: X -> fp16 tiled SW64 (16384 elems/block)
__global__ void __launch_bounds__(256) conv_kernel(const float* __restrict__ x,
                                                   const float* __restrict__ mu,
                                                   const float* __restrict__ sg,
                                                   const float* __restrict__ ep) {
    int t = threadIdx.x;
    if (blockIdx.x < 1024) {
        __shared__ float red[256];
        size_t b4 = (size_t)blockIdx.x * 4096;  // float4 index base
        float acc = 0.f;
#pragma unroll
        for (int i = 0; i < 16; i++) {
            size_t idx = b4 + (size_t)i * 256 + t;       // float4 index
            float4 m = ((const float4*)mu)[idx];
            float4 s = ((const float4*)sg)[idx];
            float4 e = ((const float4*)ep)[idx];
            float e0 = __expf(s.x), e1 = __expf(s.y), e2 = __expf(s.z), e3 = __expf(s.w);
            float w0 = m.x + e0 * e.x, w1 = m.y + e1 * e.y;
            float w2 = m.z + e2 * e.z, w3 = m.w + e3 * e.w;
            __half2 h01 = __floats2half2_rn(w0, w1);
            __half2 h23 = __floats2half2_rn(w2, w3);
            uint2 pk;
            pk.x = *reinterpret_cast<uint32_t*>(&h01);
            pk.y = *reinterpret_cast<uint32_t*>(&h23);
            int r = (int)(idx >> 10);                    // row (1024 float4/row)
            int c = ((int)idx & 1023) * 4;               // col in halves
            size_t blk = (size_t)((r >> 8) * KBLK + (c >> 5));
            uint32_t off = (uint32_t)((r & 255) * 64 + (c & 31) * 2);
            *reinterpret_cast<uint2*>((char*)g_wh + blk * TILE_BYTES + SWZ64(off)) = pk;
            acc += 4.f + 2.f * (s.x + s.y + s.z + s.w)
                       - (m.x * m.x + m.y * m.y + m.z * m.z + m.w * m.w)
                       - (e0 * e0 + e1 * e1 + e2 * e2 + e3 * e3);
        }
        red[t] = acc;
        __syncthreads();
        for (int o = 128; o > 0; o >>= 1) {
            if (t < o) red[t] += red[t + o];
            __syncthreads();
        }
        if (t == 0) g_partial[blockIdx.x] = red[0];
    } else {
        size_t b4 = (size_t)(blockIdx.x - 1024) * 4096;
#pragma unroll
        for (int i = 0; i < 16; i++) {
            size_t idx = b4 + (size_t)i * 256 + t;
            float4 v = ((const float4*)x)[idx];
            __half2 h01 = __floats2half2_rn(v.x, v.y);
            __half2 h23 = __floats2half2_rn(v.z, v.w);
            uint2 pk;
            pk.x = *reinterpret_cast<uint32_t*>(&h01);
            pk.y = *reinterpret_cast<uint32_t*>(&h23);
            int r = (int)(idx >> 10);
            int c = ((int)idx & 1023) * 4;
            size_t blk = (size_t)((r >> 8) * KBLK + (c >> 5));
            uint32_t off = (uint32_t)((r & 255) * 64 + (c & 31) * 2);
            *reinterpret_cast<uint2*>((char*)g_xh + blk * TILE_BYTES + SWZ64(off)) = pk;
        }
    }
}

// ---------------- kernel 2: bias + final KL ---------------------------------
__global__ void __launch_bounds__(1024) biaskl_kernel(const float* __restrict__ bmu,
                                                      const float* __restrict__ bsg,
                                                      const float* __restrict__ beb,
                                                      float* __restrict__ out, int klidx) {
    __shared__ float red[1024];
    int t = threadIdx.x;
    float acc = 0.f;
    for (int i = t; i < OUT_DIM; i += 1024) {
        float m = bmu[i], s = bsg[i], e = beb[i];
        float es = __expf(s);
        g_bias[i] = m + es * e;
        acc += 1.f + 2.f * s - m * m - es * es;
    }
    acc += g_partial[t];
    red[t] = acc;
    __syncthreads();
    for (int o = 512; o > 0; o >>= 1) {
        if (t < o) red[t] += red[t + o];
        __syncthreads();
    }
    if (t == 0) out[klidx] = -0.5f * red[0];
}

// ---------------- kernel 3: persistent cg2 GEMM, 256x512 tiles ---------------
// Rank r holds A rows r*128..+127 (8KB) and B output-band ni*512 + r*256..+255
// (16KB) per kstep. Two N=256 cg2 atoms per k16: atom0 (B rows 0-127/CTA) ->
// D cols 0-255, atom1 (B rows 128-255/CTA) -> D cols 256-511. cg2 col order
// interleaves rank halves -> output col group permutation {0,2,1,3}.
__global__ void __launch_bounds__(GEMM_THREADS, 1) gemm_kernel(float* __restrict__ out) {
    extern __shared__ __align__(1024) char smem[];
    uint32_t sb = smem_u32(smem);
    int tid = threadIdx.x;
    int wid = tid >> 5;
    int lid = tid & 31;

#if defined(HAS_TCGEN05)
    uint32_t rank = cluster_rank();
    int cid = blockIdx.x >> 1;
    int ntiles = (NUM_PT - 1 - cid) / NUM_CLUSTERS + 1;   // 4 or 3

    if (tid == 0) {
        for (int s = 0; s < STAGES; s++) {
            MBARRIER_INIT(sb + SM_FULL + s * 8, 1);      // local expect_tx
            MBARRIER_INIT(sb + SM_EMPTY + s * 8, 1);     // cg2 commit MC (1 arrive/CTA)
            MBARRIER_INIT(sb + SM_PEERFULL + s * 8, 1);  // rank1 fwd (used on rank0)
        }
        MBARRIER_INIT(sb + SM_DONE, 1);                  // cg2 commit MC per tile
        MBARRIER_INIT(sb + SM_TFREE, 16);                // 8 warps x 2 CTAs
        FENCE_PROXY_ASYNC();
        for (int s = 0; s < STAGES; s++) MBARRIER_ARRIVE(sb + SM_EMPTY + s * 8);  // pre-arm
        for (int i = 0; i < 16; i++) MBARRIER_ARRIVE(sb + SM_TFREE);              // pre-arm
    }
    if (wid == 8) TCGEN05_ALLOC_CG2(sb + SM_TMEMPTR, 512);
    __syncthreads();
    CLUSTER_SYNC();   // cluster-wide barrier/TMEM init before any cross-CTA traffic
    uint32_t tmem;
    asm volatile("ld.shared.b32 %0, [%1];" : "=r"(tmem) : "r"(sb + SM_TMEMPTR));

    if (wid == 9 && lid == 0) {
        // ---- producer (both CTAs): A own half (8KB) + B own band (16KB) ----
        int s = 0, ph = 0;
        for (int w = 0; w < ntiles; w++) {
            int pt = cid + w * NUM_CLUSTERS;
            int mi = pt & (NUM_MT - 1);
            int ni = pt >> 5;
            const char* srcA = (const char*)g_xh + (size_t)mi * KBLK * TILE_BYTES + rank * A_ST;
            const char* srcB = (const char*)g_wh + (size_t)(ni * 2 + rank) * KBLK * TILE_BYTES;
            for (int ks = 0; ks < KSTEPS; ks++) {
                MBARRIER_WAIT_PARITY(sb + SM_EMPTY + s * 8, ph);
                uint32_t stage_base = sb + SM_DATA + s * STAGE_BYTES;
                MBARRIER_EXPECT_TX(sb + SM_FULL + s * 8, STAGE_BYTES);
                BULK_G2S(stage_base,        srcA + (size_t)ks * TILE_BYTES, A_ST, sb + SM_FULL + s * 8);
                BULK_G2S(stage_base + A_ST, srcB + (size_t)ks * TILE_BYTES, B_ST, sb + SM_FULL + s * 8);
                if (++s == STAGES) { s = 0; ph ^= 1; }
            }
        }
    }
    if (wid == 8) {
        int s = 0, ph = 0;
        if (rank == 1) {
            // ---- forwarder: relay local stage-full to rank0 ----
            int total = ntiles * KSTEPS;
            for (int i = 0; i < total; i++) {
                MBARRIER_WAIT_PARITY(sb + SM_FULL + s * 8, ph);
                if (elect_one_pred()) MBARRIER_ARRIVE_CLUSTER(sb + SM_PEERFULL + s * 8, 0);
                if (++s == STAGES) { s = 0; ph ^= 1; }
            }
        } else {
            // ---- MMA warp (leader): 2 N=256 atoms x 2 k16 per stage ----
            for (int w = 0; w < ntiles; w++) {
                MBARRIER_WAIT_PARITY(sb + SM_TFREE, w & 1);          // D free
                for (int ks = 0; ks < KSTEPS; ks++) {
                    MBARRIER_WAIT_PARITY(sb + SM_FULL + s * 8, ph);      // own halves ready
                    MBARRIER_WAIT_PARITY(sb + SM_PEERFULL + s * 8, ph);  // peer halves ready
                    if (elect_one_pred()) {
                        uint32_t stage_base = sb + SM_DATA + s * STAGE_BYTES;
                        uint64_t ad   = make_desc64(stage_base);
                        uint64_t bdlo = make_desc64(stage_base + A_ST);         // B rows 0-127
                        uint64_t bdhi = make_desc64(stage_base + A_ST + 8192);  // B rows 128-255
                        uint32_t en = (ks == 0) ? 0u : 1u;
#pragma unroll
                        for (int k = 0; k < 2; k++) {
                            uint32_t ek = (k == 0) ? en : 1u;
                            mma_f16_ss_cg2(tmem,       ad + k * 2, bdlo + k * 2, IDESC_CG2, ek);
                            mma_f16_ss_cg2(tmem + 256, ad + k * 2, bdhi + k * 2, IDESC_CG2, ek);
                        }
                        TCGEN05_COMMIT_MC_CG2(sb + SM_EMPTY + s * 8, 0x3);  // free stage both CTAs
                    }
                    if (++s == STAGES) { s = 0; ph ^= 1; }
                }
                if (elect_one_pred()) TCGEN05_COMMIT_MC_CG2(sb + SM_DONE, 0x3);  // tile done both CTAs
            }
        }
    }
    if (wid < 8) {
        // ---- epilogue warps (both CTAs): own 128 rows x 512 cols ----
        int half = wid >> 2;          // tmem col half: 0 -> cols 0-255, 1 -> 256-511
        int w4 = wid & 3;             // TMEM subpartition (lanes w4*32..+31)
        for (int w = 0; w < ntiles; w++) {
            int pt = cid + w * NUM_CLUSTERS;
            int mi = pt & (NUM_MT - 1);
            int ni = pt >> 5;
            int row = mi * 256 + (int)rank * 128 + w4 * 32 + lid;
            float* orow = out + (size_t)row * OUT_DIM;
            MBARRIER_WAIT_PARITY(sb + SM_DONE, w & 1);
            TCGEN05_FENCE_AFTER();
#pragma unroll 1
            for (int cc = 0; cc < 8; cc++) {
                int tcol = half * 256 + cc * 32;           // tmem column of this chunk
                int g = tcol >> 7;                          // 128-col group 0..3
                int gp = (g == 1) ? 2 : ((g == 2) ? 1 : g); // cg2 rank-interleave perm
                int ocol = ni * 512 + gp * 128 + (tcol & 127);
                uint32_t r[32];
                TCGEN05_LD_32X32B_X32(r, tmem + tcol);
                TCGEN05_WAIT_LD();
                const float4* bv4 = (const float4*)(g_bias + ocol);
                float4* o4 = (float4*)(orow + ocol);
#pragma unroll
                for (int j = 0; j < 8; j++) {
                    float4 bv = bv4[j];
                    float4 v;
                    v.x = __uint_as_float(r[j * 4 + 0]) + bv.x;
                    v.y = __uint_as_float(r[j * 4 + 1]) + bv.y;
                    v.z = __uint_as_float(r[j * 4 + 2]) + bv.z;
                    v.w = __uint_as_float(r[j * 4 + 3]) + bv.w;
                    o4[j] = v;
                }
            }
            TCGEN05_FENCE_BEFORE();
            if (lid == 0) MBARRIER_ARRIVE_CLUSTER(sb + SM_TFREE, 0);   // to leader
        }
    }

    __syncthreads();
    CLUSTER_SYNC();   // all consumption of peer SMEM/TMEM done cluster-wide
    if (wid == 8) {
        TCGEN05_RELINQUISH_CG2();
        TCGEN05_DEALLOC_CG2(tmem, 512);
    }
    CLUSTER_SYNC();
#else
    // ============== correctness-only fallback (never executes on sm_103a) ====
    uint32_t rank = blockIdx.x & 1;
    int cid = blockIdx.x >> 1;
    int ntiles = (NUM_PT - 1 - cid) / NUM_CLUSTERS + 1;
    for (int w = 0; w < ntiles; w++) {
        int pt = cid + w * NUM_CLUSTERS;
        int mi = pt & (NUM_MT - 1);
        int ni = pt >> 5;
        for (int idx = tid; idx < 128 * 512; idx += GEMM_THREADS) {
            int r = mi * 256 + (int)rank * 128 + (idx >> 9);
            int c = ni * 512 + (idx & 511);
            float acc = 0.f;
            for (int k = 0; k < IN_DIM; k++) {
                size_t xblk = (size_t)((r >> 8) * KBLK + (k >> 5));
                uint32_t xoff = SWZ64((uint32_t)((r & 255) * 64 + (k & 31) * 2));
                size_t wblk = (size_t)((c >> 8) * KBLK + (k >> 5));
                uint32_t woff = SWZ64((uint32_t)((c & 255) * 64 + (k & 31) * 2));
                float xv = __half2float(*(const __half*)((const char*)g_xh + xblk * TILE_BYTES + xoff));
                float wv = __half2float(*(const __half*)((const char*)g_wh + wblk * TILE_BYTES + woff));
                acc += xv * wv;
            }
            out[(size_t)r * OUT_DIM + c] = acc + g_bias[c];
        }
    }
#endif
}

// ---------------- launch -----------------------------------------------------
extern "C" void kernel_launch(void* const* d_in, const int* in_sizes, int n_in,
                              void* d_out, int out_size) {
    const float* x   = (const float*)d_in[0];
    const float* wmu = (const float*)d_in[1];
    const float* wsg = (const float*)d_in[2];
    const float* bmu = (const float*)d_in[3];
    const float* bsg = (const float*)d_in[4];
    const float* ew  = (const float*)d_in[5];
    const float* eb  = (const float*)d_in[6];
    float* out = (float*)d_out;

    cudaFuncSetAttribute(gemm_kernel, cudaFuncAttributeMaxDynamicSharedMemorySize, GEMM_SMEM);

    // Fused conversions: blocks 0-1023 W (+KL partials), 1024-3071 X
    conv_kernel<<<3072, 256>>>(x, wmu, wsg, ew);
    biaskl_kernel<<<1, 1024>>>(bmu, bsg, eb, out, out_size - 1);

    // Persistent cg2 GEMM: 148 CTAs = 74 clusters of 2
    cudaLaunchConfig_t cfg = {};
    cfg.gridDim = dim3(148, 1, 1);
    cfg.blockDim = dim3(GEMM_THREADS, 1, 1);
    cfg.dynamicSmemBytes = GEMM_SMEM;
    cfg.stream = 0;
    cudaLaunchAttribute attrs[1];
    attrs[0].id = cudaLaunchAttributeClusterDimension;
    attrs[0].val.clusterDim.x = 2;
    attrs[0].val.clusterDim.y = 1;
    attrs[0].val.clusterDim.z = 1;
    cfg.attrs = attrs;
    cfg.numAttrs = 1;
    cudaLaunchKernelEx(&cfg, gemm_kernel, out);
}

// round 13
// speedup vs baseline: 1.1131x; 1.1131x over previous
#include <cuda_runtime.h>
#include <cuda_fp16.h>
#include <cstdint>

#define B_DIM   8192
#define IN_DIM  4096
#define OUT_DIM 4096

// ---------------- scratch (static device globals: allocation-free) ----------
// Tiled layout: 16KB blocks = (256 rows x 32 cols) of halves, 64B rows, SW64.
// block index = (row>>8)*KBLK + (col>>5); within: SWZ64((row&255)*64 + (col&31)*2)
// rows 0-127 of a block = first 8KB, rows 128-255 = second 8KB (used by cg2).
__device__ __align__(1024) __half g_xh[(size_t)B_DIM * IN_DIM];     // 64 MB
__device__ __align__(1024) __half g_wh[(size_t)OUT_DIM * IN_DIM];   // 32 MB
__device__ float g_bias[OUT_DIM];
__device__ float g_partial[1024];

// ---------------- common helpers --------------------------------------------
__device__ __forceinline__ uint32_t smem_u32(const void* p) {
    return (uint32_t)__cvta_generic_to_shared(p);
}
#define SWZ64(o) ((o) ^ (((o) >> 3) & 0x30))

// ---------------- GEMM tiling (R10 best config) ------------------------------
// Persistent: 148 CTAs as 74 clusters of 2. cg2 MMA: pair computes 256x256 tile.
// Per-CTA per TK=32 kstep: A own 128 rows (8KB) + B own N-half 128 rows (8KB).
// 12-stage ring of 16KB. D double-buffered in TMEM (slots 0/256).
#define STAGES 12
#define TK 32
#define KSTEPS (IN_DIM / TK)            // 128
#define A_ST 8192                       // 128 rows * 64B
#define STAGE_BYTES 16384               // A half + B half
#define TILE_BYTES 16384                // one gmem conv block (256 rows x 32 cols)
#define KBLK (IN_DIM / TK)              // 128 k-blocks per 256-row band
#define NUM_MT 32                       // m tiles of 256
#define NUM_NT 16                       // n tiles of 256
#define NUM_PT (NUM_MT * NUM_NT)        // 512 pair-tiles
#define NUM_CLUSTERS 74
#define SM_TMEMPTR 0
#define SM_FULL 16
#define SM_EMPTY (SM_FULL + STAGES * 8)          // 112
#define SM_PEERFULL (SM_EMPTY + STAGES * 8)      // 208
#define SM_DONE (SM_PEERFULL + STAGES * 8)       // 304
#define SM_TFREE (SM_DONE + 8)                   // 312 (2 slots x 8B)
#define SM_DATA 1024
#define GEMM_SMEM (SM_DATA + STAGES * STAGE_BYTES)  // 197632
#define GEMM_THREADS 320   // warps 0-7 epilogue, warp 8 MMA(rank0)/fwd(rank1), warp 9 producer

// ============================================================================
// Arch-feature-gated tcgen05/cluster helpers (only for sm_10Xa targets)
// ============================================================================
#if defined(__CUDA_ARCH_FEAT_SM103_ALL) || defined(__CUDA_ARCH_FEAT_SM100_ALL) || defined(__CUDA_ARCH_FEAT_SM110_ALL)
#define HAS_TCGEN05 1

__device__ __forceinline__ uint32_t elect_one_pred() {
    uint32_t pred;
    asm volatile("{\n\t.reg .pred p;\n\telect.sync _|p, 0xFFFFFFFF;\n\t"
                 "selp.b32 %0, 1, 0, p;\n\t}" : "=r"(pred));
    return pred;
}
__device__ __forceinline__ uint32_t cluster_rank() {
    uint32_t r;
    asm("mov.u32 %0, %%cluster_ctarank;" : "=r"(r));
    return r;
}
#define CLUSTER_SYNC() do { \
    asm volatile("barrier.cluster.arrive.aligned;" ::: "memory"); \
    asm volatile("barrier.cluster.wait.aligned;" ::: "memory"); \
} while (0)

#define MBARRIER_INIT(addr, count) \
    asm volatile("mbarrier.init.shared.b64 [%0], %1;" :: "r"((uint32_t)(addr)), "r"((uint32_t)(count)) : "memory")
#define MBARRIER_ARRIVE(addr) \
    asm volatile("mbarrier.arrive.shared.b64 _, [%0];" :: "r"((uint32_t)(addr)) : "memory")
#define MBARRIER_ARRIVE_CLUSTER(local_addr, target_rank) \
    asm volatile("{\n\t.reg .b32 remAddr;\n\t" \
        "mapa.shared::cluster.u32 remAddr, %0, %1;\n\t" \
        "mbarrier.arrive.shared::cluster.b64 _, [remAddr];\n\t}" \
        :: "r"((uint32_t)(local_addr)), "r"((uint32_t)(target_rank)) : "memory")
#define MBARRIER_EXPECT_TX(addr, bytes) \
    asm volatile("mbarrier.arrive.expect_tx.shared.b64 _, [%0], %1;" :: "r"((uint32_t)(addr)), "r"((uint32_t)(bytes)) : "memory")
#define MBARRIER_WAIT_PARITY(mbar_smem_addr, phase_parity) do { \
    uint32_t _mbar = (uint32_t)(mbar_smem_addr); \
    uint32_t _parity = (uint32_t)(phase_parity); \
    uint32_t _done; \
    asm volatile("{\n\t.reg .pred p;\n\t" \
        "mbarrier.try_wait.parity.acquire.cta.shared::cta.b64 p, [%1], %2;\n\t" \
        "selp.b32 %0, 1, 0, p;\n\t}" : "=r"(_done) : "r"(_mbar), "r"(_parity) : "memory"); \
    if (!_done) { \
        asm volatile("{\n\t.reg .pred P1;\n\t" \
            "WAIT_LOOP_%=:\n\t" \
            "mbarrier.try_wait.parity.acquire.cta.shared::cta.b64 P1, [%0], %1, 0x989680;\n\t" \
            "@P1 bra.uni WAIT_DONE_%=;\n\t" \
            "bra.uni WAIT_LOOP_%=;\n\t" \
            "WAIT_DONE_%=:\n\t}" :: "r"(_mbar), "r"(_parity) : "memory"); \
    } \
} while (0)

#define BULK_G2S(dst, src, bytes, mbar) \
    asm volatile("cp.async.bulk.shared::cta.global.mbarrier::complete_tx::bytes [%0], [%1], %2, [%3];" \
        :: "r"((uint32_t)(dst)), "l"(src), "r"((uint32_t)(bytes)), "r"((uint32_t)(mbar)) : "memory")

#define TCGEN05_ALLOC_CG2(smem_result_addr, nCols) \
    asm volatile("tcgen05.alloc.cta_group::2.sync.aligned.shared::cta.b32 [%0], %1;" \
        :: "r"((uint32_t)(smem_result_addr)), "r"((uint32_t)(nCols)) : "memory")
#define TCGEN05_DEALLOC_CG2(tmem_addr, nCols) \
    asm volatile("tcgen05.dealloc.cta_group::2.sync.aligned.b32 %0, %1;" :: "r"(tmem_addr), "r"((uint32_t)(nCols)))
#define TCGEN05_RELINQUISH_CG2() \
    asm volatile("tcgen05.relinquish_alloc_permit.cta_group::2.sync.aligned;")
#define TCGEN05_COMMIT_MC_CG2(mbar, mask) \
    asm volatile("tcgen05.commit.cta_group::2.mbarrier::arrive::one.shared::cluster.multicast::cluster.b64 [%0], %1;" \
        :: "r"((uint32_t)(mbar)), "h"((uint16_t)(mask)) : "memory")
#define TCGEN05_FENCE_AFTER()  asm volatile("tcgen05.fence::after_thread_sync;" ::: "memory")
#define TCGEN05_FENCE_BEFORE() asm volatile("tcgen05.fence::before_thread_sync;" ::: "memory")
#define TCGEN05_WAIT_LD()      asm volatile("tcgen05.wait::ld.sync.aligned;" ::: "memory")
#define FENCE_PROXY_ASYNC()    asm volatile("fence.proxy.async.shared::cta;" ::: "memory")

#define TCGEN05_LD_32X32B_X32(r, tmem_addr) \
    asm volatile("tcgen05.ld.sync.aligned.32x32b.x32.b32 " \
        "{%0, %1, %2, %3, %4, %5, %6, %7, " \
        " %8, %9, %10, %11, %12, %13, %14, %15, " \
        " %16, %17, %18, %19, %20, %21, %22, %23, " \
        " %24, %25, %26, %27, %28, %29, %30, %31}, [%32];" \
        : "=r"((r)[0]),  "=r"((r)[1]),  "=r"((r)[2]),  "=r"((r)[3]), \
          "=r"((r)[4]),  "=r"((r)[5]),  "=r"((r)[6]),  "=r"((r)[7]), \
          "=r"((r)[8]),  "=r"((r)[9]),  "=r"((r)[10]), "=r"((r)[11]), \
          "=r"((r)[12]), "=r"((r)[13]), "=r"((r)[14]), "=r"((r)[15]), \
          "=r"((r)[16]), "=r"((r)[17]), "=r"((r)[18]), "=r"((r)[19]), \
          "=r"((r)[20]), "=r"((r)[21]), "=r"((r)[22]), "=r"((r)[23]), \
          "=r"((r)[24]), "=r"((r)[25]), "=r"((r)[26]), "=r"((r)[27]), \
          "=r"((r)[28]), "=r"((r)[29]), "=r"((r)[30]), "=r"((r)[31]) \
        : "r"(tmem_addr))

// cg2 f16 SS MMA: M=256 across the pair, 8 disable-lane regs (all zero).
__device__ __forceinline__ void mma_f16_ss_cg2(uint32_t d, uint64_t a_desc, uint64_t b_desc,
                                               uint32_t idesc, uint32_t enable) {
    asm volatile("{\n\t.reg .pred p;\n\tsetp.ne.u32 p, %5, 0;\n\t"
        "tcgen05.mma.cta_group::2.kind::f16 [%0], %1, %2, %3, "
        "{%4, %4, %4, %4, %4, %4, %4, %4}, p;\n\t}"
        :: "r"(d), "l"(a_desc), "l"(b_desc), "r"(idesc), "r"(0u), "r"(enable) : "memory");
}
// SW64 K-major descriptor: layout=4, version=1, SBO=32 (512B per 8-row atom), LBO=1
__device__ __forceinline__ uint64_t make_desc64(uint32_t addr) {
    const uint64_t base = (4ULL << 61) | (1ULL << 46) | (32ULL << 32) | (1ULL << 16);
    return base | ((uint64_t)(addr >> 4) & 0x3FFF);
}
// F32 acc (1<<4), f16 inputs, N=256 (bits[17:22]=N>>3), M=256 (bits[24:28]=M>>4)
#define IDESC_CG2 ((1u << 4) | (32u << 17) | (16u << 24))
#endif  // arch feature

// ---------------- kernel 1: fused conversions --------------------------------
// blocks 0-1023:    W -> fp16 tiled SW64 + KL partials (16384 elems/block)
// blocks 1024-3071: X -> fp16 tiled SW64 (16384 elems/block)
__global__ void __launch_bounds__(256) conv_kernel(const float* __restrict__ x,
                                                   const float* __restrict__ mu,
                                                   const float* __restrict__ sg,
                                                   const float* __restrict__ ep) {
    int t = threadIdx.x;
    if (blockIdx.x < 1024) {
        __shared__ float red[256];
        size_t b4 = (size_t)blockIdx.x * 4096;  // float4 index base
        float acc = 0.f;
#pragma unroll
        for (int i = 0; i < 16; i++) {
            size_t idx = b4 + (size_t)i * 256 + t;       // float4 index
            float4 m = ((const float4*)mu)[idx];
            float4 s = ((const float4*)sg)[idx];
            float4 e = ((const float4*)ep)[idx];
            float e0 = __expf(s.x), e1 = __expf(s.y), e2 = __expf(s.z), e3 = __expf(s.w);
            float w0 = m.x + e0 * e.x, w1 = m.y + e1 * e.y;
            float w2 = m.z + e2 * e.z, w3 = m.w + e3 * e.w;
            __half2 h01 = __floats2half2_rn(w0, w1);
            __half2 h23 = __floats2half2_rn(w2, w3);
            uint2 pk;
            pk.x = *reinterpret_cast<uint32_t*>(&h01);
            pk.y = *reinterpret_cast<uint32_t*>(&h23);
            int r = (int)(idx >> 10);                    // row (1024 float4/row)
            int c = ((int)idx & 1023) * 4;               // col in halves
            size_t blk = (size_t)((r >> 8) * KBLK + (c >> 5));
            uint32_t off = (uint32_t)((r & 255) * 64 + (c & 31) * 2);
            *reinterpret_cast<uint2*>((char*)g_wh + blk * TILE_BYTES + SWZ64(off)) = pk;
            acc += 4.f + 2.f * (s.x + s.y + s.z + s.w)
                       - (m.x * m.x + m.y * m.y + m.z * m.z + m.w * m.w)
                       - (e0 * e0 + e1 * e1 + e2 * e2 + e3 * e3);
        }
        red[t] = acc;
        __syncthreads();
        for (int o = 128; o > 0; o >>= 1) {
            if (t < o) red[t] += red[t + o];
            __syncthreads();
        }
        if (t == 0) g_partial[blockIdx.x] = red[0];
    } else {
        size_t b4 = (size_t)(blockIdx.x - 1024) * 4096;
#pragma unroll
        for (int i = 0; i < 16; i++) {
            size_t idx = b4 + (size_t)i * 256 + t;
            float4 v = ((const float4*)x)[idx];
            __half2 h01 = __floats2half2_rn(v.x, v.y);
            __half2 h23 = __floats2half2_rn(v.z, v.w);
            uint2 pk;
            pk.x = *reinterpret_cast<uint32_t*>(&h01);
            pk.y = *reinterpret_cast<uint32_t*>(&h23);
            int r = (int)(idx >> 10);
            int c = ((int)idx & 1023) * 4;
            size_t blk = (size_t)((r >> 8) * KBLK + (c >> 5));
            uint32_t off = (uint32_t)((r & 255) * 64 + (c & 31) * 2);
            *reinterpret_cast<uint2*>((char*)g_xh + blk * TILE_BYTES + SWZ64(off)) = pk;
        }
    }
}

// ---------------- kernel 2: bias + final KL ---------------------------------
__global__ void __launch_bounds__(1024) biaskl_kernel(const float* __restrict__ bmu,
                                                      const float* __restrict__ bsg,
                                                      const float* __restrict__ beb,
                                                      float* __restrict__ out, int klidx) {
    __shared__ float red[1024];
    int t = threadIdx.x;
    float acc = 0.f;
    for (int i = t; i < OUT_DIM; i += 1024) {
        float m = bmu[i], s = bsg[i], e = beb[i];
        float es = __expf(s);
        g_bias[i] = m + es * e;
        acc += 1.f + 2.f * s - m * m - es * es;
    }
    acc += g_partial[t];
    red[t] = acc;
    __syncthreads();
    for (int o = 512; o > 0; o >>= 1) {
        if (t < o) red[t] += red[t + o];
        __syncthreads();
    }
    if (t == 0) out[klidx] = -0.5f * red[0];
}

// ---------------- kernel 3: persistent cg2 GEMM (R10 best config) ------------
// Pair computes 256x256 tiles: rank r holds A rows r*128..+127 and B cols
// (output) r*128..+127 per stage. Rank0 issues all cg2 MMAs; rank1 forwards
// its stage-full via mapa-arrive. D double-buffered in TMEM (slots 0/256).
__global__ void __launch_bounds__(GEMM_THREADS, 1) gemm_kernel(float* __restrict__ out) {
    extern __shared__ __align__(1024) char smem[];
    uint32_t sb = smem_u32(smem);
    int tid = threadIdx.x;
    int wid = tid >> 5;
    int lid = tid & 31;

#if defined(HAS_TCGEN05)
    uint32_t rank = cluster_rank();
    int cid = blockIdx.x >> 1;
    int ntiles = (NUM_PT - 1 - cid) / NUM_CLUSTERS + 1;   // 7 or 6

    if (tid == 0) {
        for (int s = 0; s < STAGES; s++) {
            MBARRIER_INIT(sb + SM_FULL + s * 8, 1);      // local expect_tx
            MBARRIER_INIT(sb + SM_EMPTY + s * 8, 1);     // cg2 commit MC (1 arrive/CTA)
            MBARRIER_INIT(sb + SM_PEERFULL + s * 8, 1);  // rank1 fwd (used on rank0)
        }
        MBARRIER_INIT(sb + SM_DONE, 1);                  // cg2 commit MC per tile
        MBARRIER_INIT(sb + SM_TFREE, 16);                // slot0: 8 warps x 2 CTAs
        MBARRIER_INIT(sb + SM_TFREE + 8, 16);            // slot1
        FENCE_PROXY_ASYNC();
        for (int s = 0; s < STAGES; s++) MBARRIER_ARRIVE(sb + SM_EMPTY + s * 8);  // pre-arm
        for (int i = 0; i < 16; i++) {                   // pre-arm both tfree slots
            MBARRIER_ARRIVE(sb + SM_TFREE);
            MBARRIER_ARRIVE(sb + SM_TFREE + 8);
        }
    }
    if (wid == 8) TCGEN05_ALLOC_CG2(sb + SM_TMEMPTR, 512);
    __syncthreads();
    CLUSTER_SYNC();   // cluster-wide barrier/TMEM init before any cross-CTA traffic
    uint32_t tmem;
    asm volatile("ld.shared.b32 %0, [%1];" : "=r"(tmem) : "r"(sb + SM_TMEMPTR));

    if (wid == 9 && lid == 0) {
        // ---- producer (both CTAs): own A half + own B half per stage ----
        int s = 0, ph = 0;
        for (int w = 0; w < ntiles; w++) {
            int pt = cid + w * NUM_CLUSTERS;
            int mi = pt & (NUM_MT - 1);
            int ni = pt >> 5;
            const char* srcA = (const char*)g_xh + (size_t)mi * KBLK * TILE_BYTES + rank * A_ST;
            const char* srcB = (const char*)g_wh + (size_t)ni * KBLK * TILE_BYTES + rank * A_ST;
            for (int ks = 0; ks < KSTEPS; ks++) {
                MBARRIER_WAIT_PARITY(sb + SM_EMPTY + s * 8, ph);
                uint32_t stage_base = sb + SM_DATA + s * STAGE_BYTES;
                MBARRIER_EXPECT_TX(sb + SM_FULL + s * 8, STAGE_BYTES);
                BULK_G2S(stage_base,        srcA + (size_t)ks * TILE_BYTES, A_ST, sb + SM_FULL + s * 8);
                BULK_G2S(stage_base + A_ST, srcB + (size_t)ks * TILE_BYTES, A_ST, sb + SM_FULL + s * 8);
                if (++s == STAGES) { s = 0; ph ^= 1; }
            }
        }
    }
    if (wid == 8) {
        int s = 0, ph = 0;
        if (rank == 1) {
            // ---- forwarder: relay local stage-full to rank0 ----
            int total = ntiles * KSTEPS;
            for (int i = 0; i < total; i++) {
                MBARRIER_WAIT_PARITY(sb + SM_FULL + s * 8, ph);
                if (elect_one_pred()) MBARRIER_ARRIVE_CLUSTER(sb + SM_PEERFULL + s * 8, 0);
                if (++s == STAGES) { s = 0; ph ^= 1; }
            }
        } else {
            // ---- MMA warp (leader): one cg2 M=256 atom x two k16 chunks/stage ----
            for (int w = 0; w < ntiles; w++) {
                MBARRIER_WAIT_PARITY(sb + SM_TFREE + (w & 1) * 8, (w >> 1) & 1);  // D slot free
                uint32_t dslot = tmem + (w & 1) * 256;
                for (int ks = 0; ks < KSTEPS; ks++) {
                    MBARRIER_WAIT_PARITY(sb + SM_FULL + s * 8, ph);      // own half ready
                    MBARRIER_WAIT_PARITY(sb + SM_PEERFULL + s * 8, ph);  // peer half ready
                    if (elect_one_pred()) {
                        uint32_t stage_base = sb + SM_DATA + s * STAGE_BYTES;
                        uint64_t ad = make_desc64(stage_base);
                        uint64_t bd = make_desc64(stage_base + A_ST);
                        uint32_t en = (ks == 0) ? 0u : 1u;
                        mma_f16_ss_cg2(dslot, ad,     bd,     IDESC_CG2, en);
                        mma_f16_ss_cg2(dslot, ad + 2, bd + 2, IDESC_CG2, 1u);
                        TCGEN05_COMMIT_MC_CG2(sb + SM_EMPTY + s * 8, 0x3);  // free stage both CTAs
                    }
                    if (++s == STAGES) { s = 0; ph ^= 1; }
                }
                if (elect_one_pred()) TCGEN05_COMMIT_MC_CG2(sb + SM_DONE, 0x3);  // tile done both CTAs
            }
        }
    }
    if (wid < 8) {
        // ---- epilogue warps (both CTAs): drain own 128 rows x 256 cols ----
        int half = wid >> 2;          // column half (0-127 / 128-255)
        int w4 = wid & 3;             // TMEM subpartition (lanes w4*32..+31)
        for (int w = 0; w < ntiles; w++) {
            int pt = cid + w * NUM_CLUSTERS;
            int mi = pt & (NUM_MT - 1);
            int ni = pt >> 5;
            int row = mi * 256 + (int)rank * 128 + w4 * 32 + lid;
            int n0 = ni * 256 + half * 128;
            float* orow = out + (size_t)row * OUT_DIM + n0;
            uint32_t tbase = tmem + (w & 1) * 256 + half * 128;
            MBARRIER_WAIT_PARITY(sb + SM_DONE, w & 1);
            TCGEN05_FENCE_AFTER();
#pragma unroll 1
            for (int cc = 0; cc < 4; cc++) {
                uint32_t r[32];
                TCGEN05_LD_32X32B_X32(r, tbase + cc * 32);
                TCGEN05_WAIT_LD();
                const float4* bv4 = (const float4*)(g_bias + n0 + cc * 32);
                float4* o4 = (float4*)(orow + cc * 32);
#pragma unroll
                for (int j = 0; j < 8; j++) {
                    float4 bv = bv4[j];
                    float4 v;
                    v.x = __uint_as_float(r[j * 4 + 0]) + bv.x;
                    v.y = __uint_as_float(r[j * 4 + 1]) + bv.y;
                    v.z = __uint_as_float(r[j * 4 + 2]) + bv.z;
                    v.w = __uint_as_float(r[j * 4 + 3]) + bv.w;
                    o4[j] = v;
                }
            }
            TCGEN05_FENCE_BEFORE();
            if (lid == 0) MBARRIER_ARRIVE_CLUSTER(sb + SM_TFREE + (w & 1) * 8, 0);  // to leader
        }
    }

    __syncthreads();
    CLUSTER_SYNC();   // all consumption of peer SMEM/TMEM done cluster-wide
    if (wid == 8) {
        TCGEN05_RELINQUISH_CG2();
        TCGEN05_DEALLOC_CG2(tmem, 512);
    }
    CLUSTER_SYNC();
#else
    // ============== correctness-only fallback (never executes on sm_103a) ====
    uint32_t rank = blockIdx.x & 1;
    int cid = blockIdx.x >> 1;
    int ntiles = (NUM_PT - 1 - cid) / NUM_CLUSTERS + 1;
    for (int w = 0; w < ntiles; w++) {
        int pt = cid + w * NUM_CLUSTERS;
        int mi = pt & (NUM_MT - 1);
        int ni = pt >> 5;
        for (int idx = tid; idx < 128 * 256; idx += GEMM_THREADS) {
            int r = mi * 256 + (int)rank * 128 + (idx >> 8);
            int c = ni * 256 + (idx & 255);
            float acc = 0.f;
            for (int k = 0; k < IN_DIM; k++) {
                size_t xblk = (size_t)((r >> 8) * KBLK + (k >> 5));
                uint32_t xoff = SWZ64((uint32_t)((r & 255) * 64 + (k & 31) * 2));
                size_t wblk = (size_t)((c >> 8) * KBLK + (k >> 5));
                uint32_t woff = SWZ64((uint32_t)((c & 255) * 64 + (k & 31) * 2));
                float xv = __half2float(*(const __half*)((const char*)g_xh + xblk * TILE_BYTES + xoff));
                float wv = __half2float(*(const __half*)((const char*)g_wh + wblk * TILE_BYTES + woff));
                acc += xv * wv;
            }
            out[(size_t)r * OUT_DIM + c] = acc + g_bias[c];
        }
    }
#endif
}

// ---------------- launch -----------------------------------------------------
extern "C" void kernel_launch(void* const* d_in, const int* in_sizes, int n_in,
                              void* d_out, int out_size) {
    const float* x   = (const float*)d_in[0];
    const float* wmu = (const float*)d_in[1];
    const float* wsg = (const float*)d_in[2];
    const float* bmu = (const float*)d_in[3];
    const float* bsg = (const float*)d_in[4];
    const float* ew  = (const float*)d_in[5];
    const float* eb  = (const float*)d_in[6];
    float* out = (float*)d_out;

    cudaFuncSetAttribute(gemm_kernel, cudaFuncAttributeMaxDynamicSharedMemorySize, GEMM_SMEM);

    // Fused conversions: blocks 0-1023 W (+KL partials), 1024-3071 X
    conv_kernel<<<3072, 256>>>(x, wmu, wsg, ew);
    biaskl_kernel<<<1, 1024>>>(bmu, bsg, eb, out, out_size - 1);

    // Persistent cg2 GEMM: 148 CTAs = 74 clusters of 2
    cudaLaunchConfig_t cfg = {};
    cfg.gridDim = dim3(148, 1, 1);
    cfg.blockDim = dim3(GEMM_THREADS, 1, 1);
    cfg.dynamicSmemBytes = GEMM_SMEM;
    cfg.stream = 0;
    cudaLaunchAttribute attrs[1];
    attrs[0].id = cudaLaunchAttributeClusterDimension;
    attrs[0].val.clusterDim.x = 2;
    attrs[0].val.clusterDim.y = 1;
    attrs[0].val.clusterDim.z = 1;
    cfg.attrs = attrs;
    cfg.numAttrs = 1;
    cudaLaunchKernelEx(&cfg, gemm_kernel, out);
}

// round 14
// speedup vs baseline: 1.1352x; 1.0198x over previous
#include <cuda_runtime.h>
#include <cuda_fp16.h>
#include <cstdint>

#define B_DIM   8192
#define IN_DIM  4096
#define OUT_DIM 4096

// ---------------- scratch (static device globals: allocation-free) ----------
// Tiled layout: 16KB blocks = (256 rows x 32 cols) of halves, 64B rows, SW64.
// block index = (row>>8)*KBLK + (col>>5); within: SWZ64((row&255)*64 + (col&31)*2)
// rows 0-127 of a block = first 8KB, rows 128-255 = second 8KB.
__device__ __align__(1024) __half g_xh[(size_t)B_DIM * IN_DIM];     // 64 MB
__device__ __align__(1024) __half g_wh[(size_t)OUT_DIM * IN_DIM];   // 32 MB
__device__ float g_bias[OUT_DIM];
__device__ float g_partial[1024];

// ---------------- common helpers --------------------------------------------
__device__ __forceinline__ uint32_t smem_u32(const void* p) {
    return (uint32_t)__cvta_generic_to_shared(p);
}
#define SWZ64(o) ((o) ^ (((o) >> 3) & 0x30))

// ---------------- GEMM tiling ------------------------------------------------
// 32 clusters of 4 CTAs (128 CTAs; cluster-4 residency limit is 132). Each
// cluster = two cg2 pairs {0,1},{2,3} computing one 256(M)x512(N) tile: pair p
// does output cols ni*512+p*256..+255. A halves multicast to {r, r+2}; B per-CTA.
// Per-CTA stage: A 8KB + B 8KB. 12-stage ring. D double-buffered (slots 0/256).
#define STAGES 12
#define TK 32
#define KSTEPS (IN_DIM / TK)            // 128
#define A_ST 8192                       // 128 rows * 64B
#define STAGE_BYTES 16384               // A half + B half
#define TILE_BYTES 16384                // one gmem conv block (256 rows x 32 cols)
#define KBLK (IN_DIM / TK)              // 128 k-blocks per 256-row band
#define NUM_MT 32                       // m tiles of 256
#define NUM_NT 8                        // n tiles of 512
#define NUM_PT (NUM_MT * NUM_NT)        // 256 tiles
#define NUM_CLUSTERS 32
#define NTILES (NUM_PT / NUM_CLUSTERS)  // 8 per cluster, exact
#define SM_TMEMPTR 0
#define SM_FULL 16
#define SM_EMPTY (SM_FULL + STAGES * 8)          // 112
#define SM_PEERFULL (SM_EMPTY + STAGES * 8)      // 208
#define SM_DONE (SM_PEERFULL + STAGES * 8)       // 304
#define SM_TFREE (SM_DONE + 8)                   // 312 (2 slots x 8B)
#define SM_DATA 1024
#define GEMM_SMEM (SM_DATA + STAGES * STAGE_BYTES)  // 197632
#define GEMM_THREADS 320   // warps 0-7 epilogue, warp 8 MMA/fwd, warp 9 producer

// ============================================================================
// Arch-feature-gated tcgen05/cluster helpers (only for sm_10Xa targets)
// ============================================================================
#if defined(__CUDA_ARCH_FEAT_SM103_ALL) || defined(__CUDA_ARCH_FEAT_SM100_ALL) || defined(__CUDA_ARCH_FEAT_SM110_ALL)
#define HAS_TCGEN05 1

__device__ __forceinline__ uint32_t elect_one_pred() {
    uint32_t pred;
    asm volatile("{\n\t.reg .pred p;\n\telect.sync _|p, 0xFFFFFFFF;\n\t"
                 "selp.b32 %0, 1, 0, p;\n\t}" : "=r"(pred));
    return pred;
}
__device__ __forceinline__ uint32_t cluster_rank() {
    uint32_t r;
    asm("mov.u32 %0, %%cluster_ctarank;" : "=r"(r));
    return r;
}
#define CLUSTER_SYNC() do { \
    asm volatile("barrier.cluster.arrive.aligned;" ::: "memory"); \
    asm volatile("barrier.cluster.wait.aligned;" ::: "memory"); \
} while (0)

#define MBARRIER_INIT(addr, count) \
    asm volatile("mbarrier.init.shared.b64 [%0], %1;" :: "r"((uint32_t)(addr)), "r"((uint32_t)(count)) : "memory")
#define MBARRIER_ARRIVE(addr) \
    asm volatile("mbarrier.arrive.shared.b64 _, [%0];" :: "r"((uint32_t)(addr)) : "memory")
#define MBARRIER_ARRIVE_CLUSTER(local_addr, target_rank) \
    asm volatile("{\n\t.reg .b32 remAddr;\n\t" \
        "mapa.shared::cluster.u32 remAddr, %0, %1;\n\t" \
        "mbarrier.arrive.shared::cluster.b64 _, [remAddr];\n\t}" \
        :: "r"((uint32_t)(local_addr)), "r"((uint32_t)(target_rank)) : "memory")
#define MBARRIER_EXPECT_TX(addr, bytes) \
    asm volatile("mbarrier.arrive.expect_tx.shared.b64 _, [%0], %1;" :: "r"((uint32_t)(addr)), "r"((uint32_t)(bytes)) : "memory")
#define MBARRIER_WAIT_PARITY(mbar_smem_addr, phase_parity) do { \
    uint32_t _mbar = (uint32_t)(mbar_smem_addr); \
    uint32_t _parity = (uint32_t)(phase_parity); \
    uint32_t _done; \
    asm volatile("{\n\t.reg .pred p;\n\t" \
        "mbarrier.try_wait.parity.acquire.cta.shared::cta.b64 p, [%1], %2;\n\t" \
        "selp.b32 %0, 1, 0, p;\n\t}" : "=r"(_done) : "r"(_mbar), "r"(_parity) : "memory"); \
    if (!_done) { \
        asm volatile("{\n\t.reg .pred P1;\n\t" \
            "WAIT_LOOP_%=:\n\t" \
            "mbarrier.try_wait.parity.acquire.cta.shared::cta.b64 P1, [%0], %1, 0x989680;\n\t" \
            "@P1 bra.uni WAIT_DONE_%=;\n\t" \
            "bra.uni WAIT_LOOP_%=;\n\t" \
            "WAIT_DONE_%=:\n\t}" :: "r"(_mbar), "r"(_parity) : "memory"); \
    } \
} while (0)

#define BULK_G2S(dst, src, bytes, mbar) \
    asm volatile("cp.async.bulk.shared::cta.global.mbarrier::complete_tx::bytes [%0], [%1], %2, [%3];" \
        :: "r"((uint32_t)(dst)), "l"(src), "r"((uint32_t)(bytes)), "r"((uint32_t)(mbar)) : "memory")
#define BULK_G2S_MC(dst, src, bytes, mbar, mask) \
    asm volatile("cp.async.bulk.shared::cluster.global.mbarrier::complete_tx::bytes.multicast::cluster [%0], [%1], %2, [%3], %4;" \
        :: "r"((uint32_t)(dst)), "l"(src), "r"((uint32_t)(bytes)), "r"((uint32_t)(mbar)), "h"((uint16_t)(mask)) : "memory")

#define TCGEN05_ALLOC_CG2(smem_result_addr, nCols) \
    asm volatile("tcgen05.alloc.cta_group::2.sync.aligned.shared::cta.b32 [%0], %1;" \
        :: "r"((uint32_t)(smem_result_addr)), "r"((uint32_t)(nCols)) : "memory")
#define TCGEN05_DEALLOC_CG2(tmem_addr, nCols) \
    asm volatile("tcgen05.dealloc.cta_group::2.sync.aligned.b32 %0, %1;" :: "r"(tmem_addr), "r"((uint32_t)(nCols)))
#define TCGEN05_RELINQUISH_CG2() \
    asm volatile("tcgen05.relinquish_alloc_permit.cta_group::2.sync.aligned;")
#define TCGEN05_COMMIT_MC_CG2(mbar, mask) \
    asm volatile("tcgen05.commit.cta_group::2.mbarrier::arrive::one.shared::cluster.multicast::cluster.b64 [%0], %1;" \
        :: "r"((uint32_t)(mbar)), "h"((uint16_t)(mask)) : "memory")
#define TCGEN05_FENCE_AFTER()  asm volatile("tcgen05.fence::after_thread_sync;" ::: "memory")
#define TCGEN05_FENCE_BEFORE() asm volatile("tcgen05.fence::before_thread_sync;" ::: "memory")
#define TCGEN05_WAIT_LD()      asm volatile("tcgen05.wait::ld.sync.aligned;" ::: "memory")
#define FENCE_PROXY_ASYNC()    asm volatile("fence.proxy.async.shared::cta;" ::: "memory")

#define TCGEN05_LD_32X32B_X32(r, tmem_addr) \
    asm volatile("tcgen05.ld.sync.aligned.32x32b.x32.b32 " \
        "{%0, %1, %2, %3, %4, %5, %6, %7, " \
        " %8, %9, %10, %11, %12, %13, %14, %15, " \
        " %16, %17, %18, %19, %20, %21, %22, %23, " \
        " %24, %25, %26, %27, %28, %29, %30, %31}, [%32];" \
        : "=r"((r)[0]),  "=r"((r)[1]),  "=r"((r)[2]),  "=r"((r)[3]), \
          "=r"((r)[4]),  "=r"((r)[5]),  "=r"((r)[6]),  "=r"((r)[7]), \
          "=r"((r)[8]),  "=r"((r)[9]),  "=r"((r)[10]), "=r"((r)[11]), \
          "=r"((r)[12]), "=r"((r)[13]), "=r"((r)[14]), "=r"((r)[15]), \
          "=r"((r)[16]), "=r"((r)[17]), "=r"((r)[18]), "=r"((r)[19]), \
          "=r"((r)[20]), "=r"((r)[21]), "=r"((r)[22]), "=r"((r)[23]), \
          "=r"((r)[24]), "=r"((r)[25]), "=r"((r)[26]), "=r"((r)[27]), \
          "=r"((r)[28]), "=r"((r)[29]), "=r"((r)[30]), "=r"((r)[31]) \
        : "r"(tmem_addr))

// cg2 f16 SS MMA: M=256 across the pair, 8 disable-lane regs (all zero).
__device__ __forceinline__ void mma_f16_ss_cg2(uint32_t d, uint64_t a_desc, uint64_t b_desc,
                                               uint32_t idesc, uint32_t enable) {
    asm volatile("{\n\t.reg .pred p;\n\tsetp.ne.u32 p, %5, 0;\n\t"
        "tcgen05.mma.cta_group::2.kind::f16 [%0], %1, %2, %3, "
        "{%4, %4, %4, %4, %4, %4, %4, %4}, p;\n\t}"
        :: "r"(d), "l"(a_desc), "l"(b_desc), "r"(idesc), "r"(0u), "r"(enable) : "memory");
}
// SW64 K-major descriptor: layout=4, version=1, SBO=32 (512B per 8-row atom), LBO=1
__device__ __forceinline__ uint64_t make_desc64(uint32_t addr) {
    const uint64_t base = (4ULL << 61) | (1ULL << 46) | (32ULL << 32) | (1ULL << 16);
    return base | ((uint64_t)(addr >> 4) & 0x3FFF);
}
// F32 acc (1<<4), f16 inputs, N=256 (bits[17:22]=N>>3), M=256 (bits[24:28]=M>>4)
#define IDESC_CG2 ((1u << 4) | (32u << 17) | (16u << 24))
#endif  // arch feature

// ---------------- kernel 1: fused conversions --------------------------------
// blocks 0-1023:    W -> fp16 tiled SW64 + KL partials (16384 elems/block)
// blocks 1024-3071: X -> fp16 tiled SW64 (16384 elems/block)
__global__ void __launch_bounds__(256) conv_kernel(const float* __restrict__ x,
                                                   const float* __restrict__ mu,
                                                   const float* __restrict__ sg,
                                                   const float* __restrict__ ep) {
    int t = threadIdx.x;
    if (blockIdx.x < 1024) {
        __shared__ float red[256];
        size_t b4 = (size_t)blockIdx.x * 4096;  // float4 index base
        float acc = 0.f;
#pragma unroll
        for (int i = 0; i < 16; i++) {
            size_t idx = b4 + (size_t)i * 256 + t;       // float4 index
            float4 m = ((const float4*)mu)[idx];
            float4 s = ((const float4*)sg)[idx];
            float4 e = ((const float4*)ep)[idx];
            float e0 = __expf(s.x), e1 = __expf(s.y), e2 = __expf(s.z), e3 = __expf(s.w);
            float w0 = m.x + e0 * e.x, w1 = m.y + e1 * e.y;
            float w2 = m.z + e2 * e.z, w3 = m.w + e3 * e.w;
            __half2 h01 = __floats2half2_rn(w0, w1);
            __half2 h23 = __floats2half2_rn(w2, w3);
            uint2 pk;
            pk.x = *reinterpret_cast<uint32_t*>(&h01);
            pk.y = *reinterpret_cast<uint32_t*>(&h23);
            int r = (int)(idx >> 10);                    // row (1024 float4/row)
            int c = ((int)idx & 1023) * 4;               // col in halves
            size_t blk = (size_t)((r >> 8) * KBLK + (c >> 5));
            uint32_t off = (uint32_t)((r & 255) * 64 + (c & 31) * 2);
            *reinterpret_cast<uint2*>((char*)g_wh + blk * TILE_BYTES + SWZ64(off)) = pk;
            acc += 4.f + 2.f * (s.x + s.y + s.z + s.w)
                       - (m.x * m.x + m.y * m.y + m.z * m.z + m.w * m.w)
                       - (e0 * e0 + e1 * e1 + e2 * e2 + e3 * e3);
        }
        red[t] = acc;
        __syncthreads();
        for (int o = 128; o > 0; o >>= 1) {
            if (t < o) red[t] += red[t + o];
            __syncthreads();
        }
        if (t == 0) g_partial[blockIdx.x] = red[0];
    } else {
        size_t b4 = (size_t)(blockIdx.x - 1024) * 4096;
#pragma unroll
        for (int i = 0; i < 16; i++) {
            size_t idx = b4 + (size_t)i * 256 + t;
            float4 v = ((const float4*)x)[idx];
            __half2 h01 = __floats2half2_rn(v.x, v.y);
            __half2 h23 = __floats2half2_rn(v.z, v.w);
            uint2 pk;
            pk.x = *reinterpret_cast<uint32_t*>(&h01);
            pk.y = *reinterpret_cast<uint32_t*>(&h23);
            int r = (int)(idx >> 10);
            int c = ((int)idx & 1023) * 4;
            size_t blk = (size_t)((r >> 8) * KBLK + (c >> 5));
            uint32_t off = (uint32_t)((r & 255) * 64 + (c & 31) * 2);
            *reinterpret_cast<uint2*>((char*)g_xh + blk * TILE_BYTES + SWZ64(off)) = pk;
        }
    }
}

// ---------------- kernel 2: bias + final KL ---------------------------------
__global__ void __launch_bounds__(1024) biaskl_kernel(const float* __restrict__ bmu,
                                                      const float* __restrict__ bsg,
                                                      const float* __restrict__ beb,
                                                      float* __restrict__ out, int klidx) {
    __shared__ float red[1024];
    int t = threadIdx.x;
    float acc = 0.f;
    for (int i = t; i < OUT_DIM; i += 1024) {
        float m = bmu[i], s = bsg[i], e = beb[i];
        float es = __expf(s);
        g_bias[i] = m + es * e;
        acc += 1.f + 2.f * s - m * m - es * es;
    }
    acc += g_partial[t];
    red[t] = acc;
    __syncthreads();
    for (int o = 512; o > 0; o >>= 1) {
        if (t < o) red[t] += red[t + o];
        __syncthreads();
    }
    if (t == 0) out[klidx] = -0.5f * red[0];
}

// ---------------- kernel 3: persistent 4-CTA cg2 GEMM, 256x512 tiles ---------
// rank r: p=r>>1 (pair), h=r&1 (half). A half h loaded by ranks 0/1, multicast
// to {h, h+2}. B band (ni*2+p) half h local. Pair leaders (ranks 0,2) issue cg2
// MMAs; forwarders (1,3) relay FULL to their leader. EMPTY needs both leaders'
// commits (count=2, mask 0xF). DONE per pair. D double-buffered (slots 0/256).
__global__ void __launch_bounds__(GEMM_THREADS, 1) gemm_kernel(float* __restrict__ out) {
    extern __shared__ __align__(1024) char smem[];
    uint32_t sb = smem_u32(smem);
    int tid = threadIdx.x;
    int wid = tid >> 5;
    int lid = tid & 31;

#if defined(HAS_TCGEN05)
    uint32_t rank = cluster_rank();
    int p = (int)(rank >> 1);
    int h = (int)(rank & 1);
    int cid = blockIdx.x >> 2;
    int mi = cid;                       // pt = cid + 32w -> mi = cid, ni = w

    if (tid == 0) {
        for (int s = 0; s < STAGES; s++) {
            MBARRIER_INIT(sb + SM_FULL + s * 8, 1);      // local expect_tx
            MBARRIER_INIT(sb + SM_EMPTY + s * 8, 2);     // both leaders' commits
            MBARRIER_INIT(sb + SM_PEERFULL + s * 8, 1);  // partner fwd (leaders use)
        }
        MBARRIER_INIT(sb + SM_DONE, 1);                  // own pair's commit per tile
        MBARRIER_INIT(sb + SM_TFREE, 16);                // slot0: 8 warps x 2 CTAs (pair)
        MBARRIER_INIT(sb + SM_TFREE + 8, 16);            // slot1
        FENCE_PROXY_ASYNC();
        for (int s = 0; s < STAGES; s++) {               // pre-arm empty phase 0 (count=2)
            MBARRIER_ARRIVE(sb + SM_EMPTY + s * 8);
            MBARRIER_ARRIVE(sb + SM_EMPTY + s * 8);
        }
        for (int i = 0; i < 16; i++) {                   // pre-arm both tfree slots
            MBARRIER_ARRIVE(sb + SM_TFREE);
            MBARRIER_ARRIVE(sb + SM_TFREE + 8);
        }
    }
    if (wid == 8) TCGEN05_ALLOC_CG2(sb + SM_TMEMPTR, 512);
    __syncthreads();
    CLUSTER_SYNC();   // cluster-wide barrier/TMEM init before any cross-CTA traffic
    uint32_t tmem;
    asm volatile("ld.shared.b32 %0, [%1];" : "=r"(tmem) : "r"(sb + SM_TMEMPTR));

    if (wid == 9 && lid == 0) {
        // ---- producer: ranks 0/1 multicast A half h to {h,h+2}; all load own B ----
        const char* srcA = (const char*)g_xh + (size_t)mi * KBLK * TILE_BYTES + h * A_ST;
        uint16_t maskA = (uint16_t)(0x5u << h);          // {h, h+2}
        int s = 0, ph = 0;
        for (int w = 0; w < NTILES; w++) {
            int ni = w;
            const char* srcB = (const char*)g_wh + (size_t)(ni * 2 + p) * KBLK * TILE_BYTES + h * A_ST;
            for (int ks = 0; ks < KSTEPS; ks++) {
                MBARRIER_WAIT_PARITY(sb + SM_EMPTY + s * 8, ph);
                uint32_t stage_base = sb + SM_DATA + s * STAGE_BYTES;
                MBARRIER_EXPECT_TX(sb + SM_FULL + s * 8, STAGE_BYTES);
                if (p == 0)
                    BULK_G2S_MC(stage_base, srcA + (size_t)ks * TILE_BYTES, A_ST,
                                sb + SM_FULL + s * 8, maskA);
                BULK_G2S(stage_base + A_ST, srcB + (size_t)ks * TILE_BYTES, A_ST,
                         sb + SM_FULL + s * 8);
                if (++s == STAGES) { s = 0; ph ^= 1; }
            }
        }
    }
    if (wid == 8) {
        int s = 0, ph = 0;
        if (h == 1) {
            // ---- forwarder (ranks 1,3): relay local stage-full to pair leader ----
            int total = NTILES * KSTEPS;
            int target = p * 2;
            for (int i = 0; i < total; i++) {
                MBARRIER_WAIT_PARITY(sb + SM_FULL + s * 8, ph);
                if (elect_one_pred()) MBARRIER_ARRIVE_CLUSTER(sb + SM_PEERFULL + s * 8, target);
                if (++s == STAGES) { s = 0; ph ^= 1; }
            }
        } else {
            // ---- pair leader (ranks 0,2): one cg2 M=256 atom x two k16 per stage ----
            uint16_t done_mask = (p == 0) ? 0x3 : 0xC;
            for (int w = 0; w < NTILES; w++) {
                MBARRIER_WAIT_PARITY(sb + SM_TFREE + (w & 1) * 8, (w >> 1) & 1);  // D slot free
                uint32_t dslot = tmem + (w & 1) * 256;
                for (int ks = 0; ks < KSTEPS; ks++) {
                    MBARRIER_WAIT_PARITY(sb + SM_FULL + s * 8, ph);      // own half ready
                    MBARRIER_WAIT_PARITY(sb + SM_PEERFULL + s * 8, ph);  // partner half ready
                    if (elect_one_pred()) {
                        uint32_t stage_base = sb + SM_DATA + s * STAGE_BYTES;
                        uint64_t ad = make_desc64(stage_base);
                        uint64_t bd = make_desc64(stage_base + A_ST);
                        uint32_t en = (ks == 0) ? 0u : 1u;
                        mma_f16_ss_cg2(dslot, ad,     bd,     IDESC_CG2, en);
                        mma_f16_ss_cg2(dslot, ad + 2, bd + 2, IDESC_CG2, 1u);
                        TCGEN05_COMMIT_MC_CG2(sb + SM_EMPTY + s * 8, 0xF);  // free stage: all 4 CTAs
                    }
                    if (++s == STAGES) { s = 0; ph ^= 1; }
                }
                if (elect_one_pred()) TCGEN05_COMMIT_MC_CG2(sb + SM_DONE, done_mask);
            }
        }
    }
    if (wid < 8) {
        // ---- epilogue warps: drain own 128 rows x 256 cols (pair's N-half) ----
        int chalf = wid >> 2;         // column half within pair (0-127 / 128-255)
        int w4 = wid & 3;             // TMEM subpartition (lanes w4*32..+31)
        int tfree_target = p * 2;
        for (int w = 0; w < NTILES; w++) {
            int ni = w;
            int row = mi * 256 + h * 128 + w4 * 32 + lid;
            int n0 = ni * 512 + p * 256 + chalf * 128;
            float* orow = out + (size_t)row * OUT_DIM + n0;
            uint32_t tbase = tmem + (w & 1) * 256 + chalf * 128;
            MBARRIER_WAIT_PARITY(sb + SM_DONE, w & 1);
            TCGEN05_FENCE_AFTER();
#pragma unroll 1
            for (int cc = 0; cc < 4; cc++) {
                uint32_t r[32];
                TCGEN05_LD_32X32B_X32(r, tbase + cc * 32);
                TCGEN05_WAIT_LD();
                const float4* bv4 = (const float4*)(g_bias + n0 + cc * 32);
                float4* o4 = (float4*)(orow + cc * 32);
#pragma unroll
                for (int j = 0; j < 8; j++) {
                    float4 bv = bv4[j];
                    float4 v;
                    v.x = __uint_as_float(r[j * 4 + 0]) + bv.x;
                    v.y = __uint_as_float(r[j * 4 + 1]) + bv.y;
                    v.z = __uint_as_float(r[j * 4 + 2]) + bv.z;
                    v.w = __uint_as_float(r[j * 4 + 3]) + bv.w;
                    o4[j] = v;
                }
            }
            TCGEN05_FENCE_BEFORE();
            if (lid == 0) MBARRIER_ARRIVE_CLUSTER(sb + SM_TFREE + (w & 1) * 8, tfree_target);
        }
    }

    __syncthreads();
    CLUSTER_SYNC();   // all consumption of peer SMEM/TMEM done cluster-wide
    if (wid == 8) {
        TCGEN05_RELINQUISH_CG2();
        TCGEN05_DEALLOC_CG2(tmem, 512);
    }
    CLUSTER_SYNC();
#else
    // ============== correctness-only fallback (never executes on sm_103a) ====
    uint32_t rank = blockIdx.x & 3;
    int p = (int)(rank >> 1), h = (int)(rank & 1);
    int cid = blockIdx.x >> 2;
    int mi = cid;
    for (int w = 0; w < NTILES; w++) {
        int ni = w;
        for (int idx = tid; idx < 128 * 256; idx += GEMM_THREADS) {
            int r = mi * 256 + h * 128 + (idx >> 8);
            int c = ni * 512 + p * 256 + (idx & 255);
            float acc = 0.f;
            for (int k = 0; k < IN_DIM; k++) {
                size_t xblk = (size_t)((r >> 8) * KBLK + (k >> 5));
                uint32_t xoff = SWZ64((uint32_t)((r & 255) * 64 + (k & 31) * 2));
                size_t wblk = (size_t)((c >> 8) * KBLK + (k >> 5));
                uint32_t woff = SWZ64((uint32_t)((c & 255) * 64 + (k & 31) * 2));
                float xv = __half2float(*(const __half*)((const char*)g_xh + xblk * TILE_BYTES + xoff));
                float wv = __half2float(*(const __half*)((const char*)g_wh + wblk * TILE_BYTES + woff));
                acc += xv * wv;
            }
            out[(size_t)r * OUT_DIM + c] = acc + g_bias[c];
        }
    }
#endif
}

// ---------------- launch -----------------------------------------------------
extern "C" void kernel_launch(void* const* d_in, const int* in_sizes, int n_in,
                              void* d_out, int out_size) {
    const float* x   = (const float*)d_in[0];
    const float* wmu = (const float*)d_in[1];
    const float* wsg = (const float*)d_in[2];
    const float* bmu = (const float*)d_in[3];
    const float* bsg = (const float*)d_in[4];
    const float* ew  = (const float*)d_in[5];
    const float* eb  = (const float*)d_in[6];
    float* out = (float*)d_out;

    cudaFuncSetAttribute(gemm_kernel, cudaFuncAttributeMaxDynamicSharedMemorySize, GEMM_SMEM);

    // Fused conversions: blocks 0-1023 W (+KL partials), 1024-3071 X
    conv_kernel<<<3072, 256>>>(x, wmu, wsg, ew);
    biaskl_kernel<<<1, 1024>>>(bmu, bsg, eb, out, out_size - 1);

    // Persistent 4-CTA-cluster GEMM: 128 CTAs = 32 clusters of 4
    cudaLaunchConfig_t cfg = {};
    cfg.gridDim = dim3(128, 1, 1);
    cfg.blockDim = dim3(GEMM_THREADS, 1, 1);
    cfg.dynamicSmemBytes = GEMM_SMEM;
    cfg.stream = 0;
    cudaLaunchAttribute attrs[1];
    attrs[0].id = cudaLaunchAttributeClusterDimension;
    attrs[0].val.clusterDim.x = 4;
    attrs[0].val.clusterDim.y = 1;
    attrs[0].val.clusterDim.z = 1;
    cfg.attrs = attrs;
    cfg.numAttrs = 1;
    cudaLaunchKernelEx(&cfg, gemm_kernel, out);
}

// round 15
// speedup vs baseline: 1.1754x; 1.0354x over previous
#include <cuda_runtime.h>
#include <cuda_fp16.h>
#include <cstdint>

#define B_DIM   8192
#define IN_DIM  4096
#define OUT_DIM 4096

// ---------------- scratch (static device globals: allocation-free) ----------
// Tiled layout: 16KB blocks = (256 rows x 32 cols) of halves, 64B rows, SW64.
// block index = (row>>8)*KBLK + (col>>5); within: SWZ64((row&255)*64 + (col&31)*2)
// rows 0-127 of a block = first 8KB, rows 128-255 = second 8KB.
__device__ __align__(1024) __half g_xh[(size_t)B_DIM * IN_DIM];     // 64 MB
__device__ __align__(1024) __half g_wh[(size_t)OUT_DIM * IN_DIM];   // 32 MB
__device__ float g_bias[OUT_DIM];
__device__ float g_partial[1024];

// ---------------- common helpers --------------------------------------------
__device__ __forceinline__ uint32_t smem_u32(const void* p) {
    return (uint32_t)__cvta_generic_to_shared(p);
}
#define SWZ64(o) ((o) ^ (((o) >> 3) & 0x30))

// ---------------- GEMM tiling ------------------------------------------------
// 32 clusters of 4 CTAs (128 CTAs). Cluster = two cg2 pairs {0,1},{2,3}, one
// 256(M)x512(N) tile; pair p owns cols ni*512+p*256. A halves multicast {r,r+2}.
// Stage = TK=64: A sub-chunks (8KB+8KB) + B sub-chunks (8KB+8KB) = 32KB.
// 6-stage ring; one barrier set per 512 MMA cycles (sync amortization).
// D double-buffered in TMEM (slots 0/256).
#define STAGES 6
#define KSTEPS 64                       // IN_DIM / 64
#define A_ST 8192                       // one 128-row x 32-col sub-chunk
#define STAGE_BYTES 32768               // A0,A1,B0,B1
#define OFF_A0 0
#define OFF_A1 8192
#define OFF_B0 16384
#define OFF_B1 24576
#define TILE_BYTES 16384                // one gmem conv block (256 rows x 32 cols)
#define KBLK 128                        // 16KB k-blocks per 256-row band
#define NUM_MT 32
#define NUM_NT 8
#define NUM_PT (NUM_MT * NUM_NT)        // 256 tiles
#define NUM_CLUSTERS 32
#define NTILES (NUM_PT / NUM_CLUSTERS)  // 8 per cluster, exact
#define SM_TMEMPTR 0
#define SM_FULL 16
#define SM_EMPTY (SM_FULL + STAGES * 8)          // 64
#define SM_PEERFULL (SM_EMPTY + STAGES * 8)      // 112
#define SM_DONE (SM_PEERFULL + STAGES * 8)       // 160
#define SM_TFREE (SM_DONE + 8)                   // 168 (2 slots x 8B)
#define SM_DATA 1024
#define GEMM_SMEM (SM_DATA + STAGES * STAGE_BYTES)  // 197632
#define GEMM_THREADS 320   // warps 0-7 epilogue, warp 8 MMA/fwd, warp 9 producer

// ============================================================================
// Arch-feature-gated tcgen05/cluster helpers (only for sm_10Xa targets)
// ============================================================================
#if defined(__CUDA_ARCH_FEAT_SM103_ALL) || defined(__CUDA_ARCH_FEAT_SM100_ALL) || defined(__CUDA_ARCH_FEAT_SM110_ALL)
#define HAS_TCGEN05 1

__device__ __forceinline__ uint32_t elect_one_pred() {
    uint32_t pred;
    asm volatile("{\n\t.reg .pred p;\n\telect.sync _|p, 0xFFFFFFFF;\n\t"
                 "selp.b32 %0, 1, 0, p;\n\t}" : "=r"(pred));
    return pred;
}
__device__ __forceinline__ uint32_t cluster_rank() {
    uint32_t r;
    asm("mov.u32 %0, %%cluster_ctarank;" : "=r"(r));
    return r;
}
#define CLUSTER_SYNC() do { \
    asm volatile("barrier.cluster.arrive.aligned;" ::: "memory"); \
    asm volatile("barrier.cluster.wait.aligned;" ::: "memory"); \
} while (0)

#define MBARRIER_INIT(addr, count) \
    asm volatile("mbarrier.init.shared.b64 [%0], %1;" :: "r"((uint32_t)(addr)), "r"((uint32_t)(count)) : "memory")
#define MBARRIER_ARRIVE(addr) \
    asm volatile("mbarrier.arrive.shared.b64 _, [%0];" :: "r"((uint32_t)(addr)) : "memory")
#define MBARRIER_ARRIVE_CLUSTER(local_addr, target_rank) \
    asm volatile("{\n\t.reg .b32 remAddr;\n\t" \
        "mapa.shared::cluster.u32 remAddr, %0, %1;\n\t" \
        "mbarrier.arrive.shared::cluster.b64 _, [remAddr];\n\t}" \
        :: "r"((uint32_t)(local_addr)), "r"((uint32_t)(target_rank)) : "memory")
#define MBARRIER_EXPECT_TX(addr, bytes) \
    asm volatile("mbarrier.arrive.expect_tx.shared.b64 _, [%0], %1;" :: "r"((uint32_t)(addr)), "r"((uint32_t)(bytes)) : "memory")
#define MBARRIER_WAIT_PARITY(mbar_smem_addr, phase_parity) do { \
    uint32_t _mbar = (uint32_t)(mbar_smem_addr); \
    uint32_t _parity = (uint32_t)(phase_parity); \
    uint32_t _done; \
    asm volatile("{\n\t.reg .pred p;\n\t" \
        "mbarrier.try_wait.parity.acquire.cta.shared::cta.b64 p, [%1], %2;\n\t" \
        "selp.b32 %0, 1, 0, p;\n\t}" : "=r"(_done) : "r"(_mbar), "r"(_parity) : "memory"); \
    if (!_done) { \
        asm volatile("{\n\t.reg .pred P1;\n\t" \
            "WAIT_LOOP_%=:\n\t" \
            "mbarrier.try_wait.parity.acquire.cta.shared::cta.b64 P1, [%0], %1, 0x989680;\n\t" \
            "@P1 bra.uni WAIT_DONE_%=;\n\t" \
            "bra.uni WAIT_LOOP_%=;\n\t" \
            "WAIT_DONE_%=:\n\t}" :: "r"(_mbar), "r"(_parity) : "memory"); \
    } \
} while (0)

#define BULK_G2S(dst, src, bytes, mbar) \
    asm volatile("cp.async.bulk.shared::cta.global.mbarrier::complete_tx::bytes [%0], [%1], %2, [%3];" \
        :: "r"((uint32_t)(dst)), "l"(src), "r"((uint32_t)(bytes)), "r"((uint32_t)(mbar)) : "memory")
#define BULK_G2S_MC(dst, src, bytes, mbar, mask) \
    asm volatile("cp.async.bulk.shared::cluster.global.mbarrier::complete_tx::bytes.multicast::cluster [%0], [%1], %2, [%3], %4;" \
        :: "r"((uint32_t)(dst)), "l"(src), "r"((uint32_t)(bytes)), "r"((uint32_t)(mbar)), "h"((uint16_t)(mask)) : "memory")

#define TCGEN05_ALLOC_CG2(smem_result_addr, nCols) \
    asm volatile("tcgen05.alloc.cta_group::2.sync.aligned.shared::cta.b32 [%0], %1;" \
        :: "r"((uint32_t)(smem_result_addr)), "r"((uint32_t)(nCols)) : "memory")
#define TCGEN05_DEALLOC_CG2(tmem_addr, nCols) \
    asm volatile("tcgen05.dealloc.cta_group::2.sync.aligned.b32 %0, %1;" :: "r"(tmem_addr), "r"((uint32_t)(nCols)))
#define TCGEN05_RELINQUISH_CG2() \
    asm volatile("tcgen05.relinquish_alloc_permit.cta_group::2.sync.aligned;")
#define TCGEN05_COMMIT_MC_CG2(mbar, mask) \
    asm volatile("tcgen05.commit.cta_group::2.mbarrier::arrive::one.shared::cluster.multicast::cluster.b64 [%0], %1;" \
        :: "r"((uint32_t)(mbar)), "h"((uint16_t)(mask)) : "memory")
#define TCGEN05_FENCE_AFTER()  asm volatile("tcgen05.fence::after_thread_sync;" ::: "memory")
#define TCGEN05_FENCE_BEFORE() asm volatile("tcgen05.fence::before_thread_sync;" ::: "memory")
#define TCGEN05_WAIT_LD()      asm volatile("tcgen05.wait::ld.sync.aligned;" ::: "memory")
#define FENCE_PROXY_ASYNC()    asm volatile("fence.proxy.async.shared::cta;" ::: "memory")

#define TCGEN05_LD_32X32B_X32(r, tmem_addr) \
    asm volatile("tcgen05.ld.sync.aligned.32x32b.x32.b32 " \
        "{%0, %1, %2, %3, %4, %5, %6, %7, " \
        " %8, %9, %10, %11, %12, %13, %14, %15, " \
        " %16, %17, %18, %19, %20, %21, %22, %23, " \
        " %24, %25, %26, %27, %28, %29, %30, %31}, [%32];" \
        : "=r"((r)[0]),  "=r"((r)[1]),  "=r"((r)[2]),  "=r"((r)[3]), \
          "=r"((r)[4]),  "=r"((r)[5]),  "=r"((r)[6]),  "=r"((r)[7]), \
          "=r"((r)[8]),  "=r"((r)[9]),  "=r"((r)[10]), "=r"((r)[11]), \
          "=r"((r)[12]), "=r"((r)[13]), "=r"((r)[14]), "=r"((r)[15]), \
          "=r"((r)[16]), "=r"((r)[17]), "=r"((r)[18]), "=r"((r)[19]), \
          "=r"((r)[20]), "=r"((r)[21]), "=r"((r)[22]), "=r"((r)[23]), \
          "=r"((r)[24]), "=r"((r)[25]), "=r"((r)[26]), "=r"((r)[27]), \
          "=r"((r)[28]), "=r"((r)[29]), "=r"((r)[30]), "=r"((r)[31]) \
        : "r"(tmem_addr))

// cg2 f16 SS MMA: M=256 across the pair, 8 disable-lane regs (all zero).
__device__ __forceinline__ void mma_f16_ss_cg2(uint32_t d, uint64_t a_desc, uint64_t b_desc,
                                               uint32_t idesc, uint32_t enable) {
    asm volatile("{\n\t.reg .pred p;\n\tsetp.ne.u32 p, %5, 0;\n\t"
        "tcgen05.mma.cta_group::2.kind::f16 [%0], %1, %2, %3, "
        "{%4, %4, %4, %4, %4, %4, %4, %4}, p;\n\t}"
        :: "r"(d), "l"(a_desc), "l"(b_desc), "r"(idesc), "r"(0u), "r"(enable) : "memory");
}
// SW64 K-major descriptor: layout=4, version=1, SBO=32 (512B per 8-row atom), LBO=1
__device__ __forceinline__ uint64_t make_desc64(uint32_t addr) {
    const uint64_t base = (4ULL << 61) | (1ULL << 46) | (32ULL << 32) | (1ULL << 16);
    return base | ((uint64_t)(addr >> 4) & 0x3FFF);
}
// F32 acc (1<<4), f16 inputs, N=256 (bits[17:22]=N>>3), M=256 (bits[24:28]=M>>4)
#define IDESC_CG2 ((1u << 4) | (32u << 17) | (16u << 24))
#endif  // arch feature

// ---------------- kernel 1: fused conversions --------------------------------
// blocks 0-1023:    W -> fp16 tiled SW64 + KL partials (16384 elems/block)
// blocks 1024-3071: X -> fp16 tiled SW64 (16384 elems/block)
__global__ void __launch_bounds__(256) conv_kernel(const float* __restrict__ x,
                                                   const float* __restrict__ mu,
                                                   const float* __restrict__ sg,
                                                   const float* __restrict__ ep) {
    int t = threadIdx.x;
    if (blockIdx.x < 1024) {
        __shared__ float red[256];
        size_t b4 = (size_t)blockIdx.x * 4096;  // float4 index base
        float acc = 0.f;
#pragma unroll
        for (int i = 0; i < 16; i++) {
            size_t idx = b4 + (size_t)i * 256 + t;       // float4 index
            float4 m = ((const float4*)mu)[idx];
            float4 s = ((const float4*)sg)[idx];
            float4 e = ((const float4*)ep)[idx];
            float e0 = __expf(s.x), e1 = __expf(s.y), e2 = __expf(s.z), e3 = __expf(s.w);
            float w0 = m.x + e0 * e.x, w1 = m.y + e1 * e.y;
            float w2 = m.z + e2 * e.z, w3 = m.w + e3 * e.w;
            __half2 h01 = __floats2half2_rn(w0, w1);
            __half2 h23 = __floats2half2_rn(w2, w3);
            uint2 pk;
            pk.x = *reinterpret_cast<uint32_t*>(&h01);
            pk.y = *reinterpret_cast<uint32_t*>(&h23);
            int r = (int)(idx >> 10);                    // row (1024 float4/row)
            int c = ((int)idx & 1023) * 4;               // col in halves
            size_t blk = (size_t)((r >> 8) * KBLK + (c >> 5));
            uint32_t off = (uint32_t)((r & 255) * 64 + (c & 31) * 2);
            *reinterpret_cast<uint2*>((char*)g_wh + blk * TILE_BYTES + SWZ64(off)) = pk;
            acc += 4.f + 2.f * (s.x + s.y + s.z + s.w)
                       - (m.x * m.x + m.y * m.y + m.z * m.z + m.w * m.w)
                       - (e0 * e0 + e1 * e1 + e2 * e2 + e3 * e3);
        }
        red[t] = acc;
        __syncthreads();
        for (int o = 128; o > 0; o >>= 1) {
            if (t < o) red[t] += red[t + o];
            __syncthreads();
        }
        if (t == 0) g_partial[blockIdx.x] = red[0];
    } else {
        size_t b4 = (size_t)(blockIdx.x - 1024) * 4096;
#pragma unroll
        for (int i = 0; i < 16; i++) {
            size_t idx = b4 + (size_t)i * 256 + t;
            float4 v = ((const float4*)x)[idx];
            __half2 h01 = __floats2half2_rn(v.x, v.y);
            __half2 h23 = __floats2half2_rn(v.z, v.w);
            uint2 pk;
            pk.x = *reinterpret_cast<uint32_t*>(&h01);
            pk.y = *reinterpret_cast<uint32_t*>(&h23);
            int r = (int)(idx >> 10);
            int c = ((int)idx & 1023) * 4;
            size_t blk = (size_t)((r >> 8) * KBLK + (c >> 5));
            uint32_t off = (uint32_t)((r & 255) * 64 + (c & 31) * 2);
            *reinterpret_cast<uint2*>((char*)g_xh + blk * TILE_BYTES + SWZ64(off)) = pk;
        }
    }
}

// ---------------- kernel 2: bias + final KL ---------------------------------
__global__ void __launch_bounds__(1024) biaskl_kernel(const float* __restrict__ bmu,
                                                      const float* __restrict__ bsg,
                                                      const float* __restrict__ beb,
                                                      float* __restrict__ out, int klidx) {
    __shared__ float red[1024];
    int t = threadIdx.x;
    float acc = 0.f;
    for (int i = t; i < OUT_DIM; i += 1024) {
        float m = bmu[i], s = bsg[i], e = beb[i];
        float es = __expf(s);
        g_bias[i] = m + es * e;
        acc += 1.f + 2.f * s - m * m - es * es;
    }
    acc += g_partial[t];
    red[t] = acc;
    __syncthreads();
    for (int o = 512; o > 0; o >>= 1) {
        if (t < o) red[t] += red[t + o];
        __syncthreads();
    }
    if (t == 0) out[klidx] = -0.5f * red[0];
}

// ---------------- kernel 3: persistent 4-CTA cg2 GEMM, 256x512 tiles ---------
// rank r: p=r>>1 (pair), h=r&1 (half). A half h loaded by ranks 0/1, multicast
// to {h, h+2}. B band (ni*2+p) half h local. Pair leaders (ranks 0,2) issue cg2
// MMAs; forwarders (1,3) relay FULL to their leader. Stage covers TK=64 (two
// 8KB sub-chunks each of A and B) -> one sync chain per 512 MMA cycles.
__global__ void __launch_bounds__(GEMM_THREADS, 1) gemm_kernel(float* __restrict__ out) {
    extern __shared__ __align__(1024) char smem[];
    uint32_t sb = smem_u32(smem);
    int tid = threadIdx.x;
    int wid = tid >> 5;
    int lid = tid & 31;

#if defined(HAS_TCGEN05)
    uint32_t rank = cluster_rank();
    int p = (int)(rank >> 1);
    int h = (int)(rank & 1);
    int cid = blockIdx.x >> 2;
    int mi = cid;                       // pt = cid + 32w -> mi = cid, ni = w

    if (tid == 0) {
        for (int s = 0; s < STAGES; s++) {
            MBARRIER_INIT(sb + SM_FULL + s * 8, 1);      // local expect_tx
            MBARRIER_INIT(sb + SM_EMPTY + s * 8, 2);     // both leaders' commits
            MBARRIER_INIT(sb + SM_PEERFULL + s * 8, 1);  // partner fwd (leaders use)
        }
        MBARRIER_INIT(sb + SM_DONE, 1);                  // own pair's commit per tile
        MBARRIER_INIT(sb + SM_TFREE, 16);                // slot0: 8 warps x 2 CTAs (pair)
        MBARRIER_INIT(sb + SM_TFREE + 8, 16);            // slot1
        FENCE_PROXY_ASYNC();
        for (int s = 0; s < STAGES; s++) {               // pre-arm empty phase 0 (count=2)
            MBARRIER_ARRIVE(sb + SM_EMPTY + s * 8);
            MBARRIER_ARRIVE(sb + SM_EMPTY + s * 8);
        }
        for (int i = 0; i < 16; i++) {                   // pre-arm both tfree slots
            MBARRIER_ARRIVE(sb + SM_TFREE);
            MBARRIER_ARRIVE(sb + SM_TFREE + 8);
        }
    }
    if (wid == 8) TCGEN05_ALLOC_CG2(sb + SM_TMEMPTR, 512);
    __syncthreads();
    CLUSTER_SYNC();   // cluster-wide barrier/TMEM init before any cross-CTA traffic
    uint32_t tmem;
    asm volatile("ld.shared.b32 %0, [%1];" : "=r"(tmem) : "r"(sb + SM_TMEMPTR));

    if (wid == 9 && lid == 0) {
        // ---- producer: ranks 0/1 multicast A half h to {h,h+2}; all load own B ----
        const char* srcA = (const char*)g_xh + (size_t)mi * KBLK * TILE_BYTES + h * A_ST;
        uint16_t maskA = (uint16_t)(0x5u << h);          // {h, h+2}
        int s = 0, ph = 0;
        for (int w = 0; w < NTILES; w++) {
            int ni = w;
            const char* srcB = (const char*)g_wh + (size_t)(ni * 2 + p) * KBLK * TILE_BYTES + h * A_ST;
            for (int ks = 0; ks < KSTEPS; ks++) {
                MBARRIER_WAIT_PARITY(sb + SM_EMPTY + s * 8, ph);
                uint32_t stage_base = sb + SM_DATA + s * STAGE_BYTES;
                size_t g0 = (size_t)(ks * 2) * TILE_BYTES;
                size_t g1 = (size_t)(ks * 2 + 1) * TILE_BYTES;
                MBARRIER_EXPECT_TX(sb + SM_FULL + s * 8, STAGE_BYTES);
                if (p == 0) {
                    BULK_G2S_MC(stage_base + OFF_A0, srcA + g0, A_ST, sb + SM_FULL + s * 8, maskA);
                    BULK_G2S_MC(stage_base + OFF_A1, srcA + g1, A_ST, sb + SM_FULL + s * 8, maskA);
                }
                BULK_G2S(stage_base + OFF_B0, srcB + g0, A_ST, sb + SM_FULL + s * 8);
                BULK_G2S(stage_base + OFF_B1, srcB + g1, A_ST, sb + SM_FULL + s * 8);
                if (++s == STAGES) { s = 0; ph ^= 1; }
            }
        }
    }
    if (wid == 8) {
        int s = 0, ph = 0;
        if (h == 1) {
            // ---- forwarder (ranks 1,3): relay local stage-full to pair leader ----
            int total = NTILES * KSTEPS;
            int target = p * 2;
            for (int i = 0; i < total; i++) {
                MBARRIER_WAIT_PARITY(sb + SM_FULL + s * 8, ph);
                if (elect_one_pred()) MBARRIER_ARRIVE_CLUSTER(sb + SM_PEERFULL + s * 8, target);
                if (++s == STAGES) { s = 0; ph ^= 1; }
            }
        } else {
            // ---- pair leader (ranks 0,2): 4 cg2 dispatches (2 sub-chunks x 2 k16) ----
            uint16_t done_mask = (p == 0) ? 0x3 : 0xC;
            for (int w = 0; w < NTILES; w++) {
                MBARRIER_WAIT_PARITY(sb + SM_TFREE + (w & 1) * 8, (w >> 1) & 1);  // D slot free
                uint32_t dslot = tmem + (w & 1) * 256;
                for (int ks = 0; ks < KSTEPS; ks++) {
                    MBARRIER_WAIT_PARITY(sb + SM_FULL + s * 8, ph);      // own halves ready
                    MBARRIER_WAIT_PARITY(sb + SM_PEERFULL + s * 8, ph);  // partner halves ready
                    if (elect_one_pred()) {
                        uint32_t stage_base = sb + SM_DATA + s * STAGE_BYTES;
                        uint64_t a0 = make_desc64(stage_base + OFF_A0);
                        uint64_t a1 = make_desc64(stage_base + OFF_A1);
                        uint64_t b0 = make_desc64(stage_base + OFF_B0);
                        uint64_t b1 = make_desc64(stage_base + OFF_B1);
                        uint32_t en = (ks == 0) ? 0u : 1u;
                        mma_f16_ss_cg2(dslot, a0,     b0,     IDESC_CG2, en);
                        mma_f16_ss_cg2(dslot, a0 + 2, b0 + 2, IDESC_CG2, 1u);
                        mma_f16_ss_cg2(dslot, a1,     b1,     IDESC_CG2, 1u);
                        mma_f16_ss_cg2(dslot, a1 + 2, b1 + 2, IDESC_CG2, 1u);
                        TCGEN05_COMMIT_MC_CG2(sb + SM_EMPTY + s * 8, 0xF);  // free stage: all 4 CTAs
                    }
                    if (++s == STAGES) { s = 0; ph ^= 1; }
                }
                if (elect_one_pred()) TCGEN05_COMMIT_MC_CG2(sb + SM_DONE, done_mask);
            }
        }
    }
    if (wid < 8) {
        // ---- epilogue warps: drain own 128 rows x 256 cols (pair's N-half) ----
        int chalf = wid >> 2;         // column half within pair (0-127 / 128-255)
        int w4 = wid & 3;             // TMEM subpartition (lanes w4*32..+31)
        int tfree_target = p * 2;
        for (int w = 0; w < NTILES; w++) {
            int ni = w;
            int row = mi * 256 + h * 128 + w4 * 32 + lid;
            int n0 = ni * 512 + p * 256 + chalf * 128;
            float* orow = out + (size_t)row * OUT_DIM + n0;
            uint32_t tbase = tmem + (w & 1) * 256 + chalf * 128;
            MBARRIER_WAIT_PARITY(sb + SM_DONE, w & 1);
            TCGEN05_FENCE_AFTER();
#pragma unroll 1
            for (int cc = 0; cc < 4; cc++) {
                uint32_t r[32];
                TCGEN05_LD_32X32B_X32(r, tbase + cc * 32);
                TCGEN05_WAIT_LD();
                const float4* bv4 = (const float4*)(g_bias + n0 + cc * 32);
                float4* o4 = (float4*)(orow + cc * 32);
#pragma unroll
                for (int j = 0; j < 8; j++) {
                    float4 bv = bv4[j];
                    float4 v;
                    v.x = __uint_as_float(r[j * 4 + 0]) + bv.x;
                    v.y = __uint_as_float(r[j * 4 + 1]) + bv.y;
                    v.z = __uint_as_float(r[j * 4 + 2]) + bv.z;
                    v.w = __uint_as_float(r[j * 4 + 3]) + bv.w;
                    o4[j] = v;
                }
            }
            TCGEN05_FENCE_BEFORE();
            if (lid == 0) MBARRIER_ARRIVE_CLUSTER(sb + SM_TFREE + (w & 1) * 8, tfree_target);
        }
    }

    __syncthreads();
    CLUSTER_SYNC();   // all consumption of peer SMEM/TMEM done cluster-wide
    if (wid == 8) {
        TCGEN05_RELINQUISH_CG2();
        TCGEN05_DEALLOC_CG2(tmem, 512);
    }
    CLUSTER_SYNC();
#else
    // ============== correctness-only fallback (never executes on sm_103a) ====
    uint32_t rank = blockIdx.x & 3;
    int p = (int)(rank >> 1), h = (int)(rank & 1);
    int cid = blockIdx.x >> 2;
    int mi = cid;
    for (int w = 0; w < NTILES; w++) {
        int ni = w;
        for (int idx = tid; idx < 128 * 256; idx += GEMM_THREADS) {
            int r = mi * 256 + h * 128 + (idx >> 8);
            int c = ni * 512 + p * 256 + (idx & 255);
            float acc = 0.f;
            for (int k = 0; k < IN_DIM; k++) {
                size_t xblk = (size_t)((r >> 8) * KBLK + (k >> 5));
                uint32_t xoff = SWZ64((uint32_t)((r & 255) * 64 + (k & 31) * 2));
                size_t wblk = (size_t)((c >> 8) * KBLK + (k >> 5));
                uint32_t woff = SWZ64((uint32_t)((c & 255) * 64 + (k & 31) * 2));
                float xv = __half2float(*(const __half*)((const char*)g_xh + xblk * TILE_BYTES + xoff));
                float wv = __half2float(*(const __half*)((const char*)g_wh + wblk * TILE_BYTES + woff));
                acc += xv * wv;
            }
            out[(size_t)r * OUT_DIM + c] = acc + g_bias[c];
        }
    }
#endif
}

// ---------------- launch -----------------------------------------------------
extern "C" void kernel_launch(void* const* d_in, const int* in_sizes, int n_in,
                              void* d_out, int out_size) {
    const float* x   = (const float*)d_in[0];
    const float* wmu = (const float*)d_in[1];
    const float* wsg = (const float*)d_in[2];
    const float* bmu = (const float*)d_in[3];
    const float* bsg = (const float*)d_in[4];
    const float* ew  = (const float*)d_in[5];
    const float* eb  = (const float*)d_in[6];
    float* out = (float*)d_out;

    cudaFuncSetAttribute(gemm_kernel, cudaFuncAttributeMaxDynamicSharedMemorySize, GEMM_SMEM);

    // Fused conversions: blocks 0-1023 W (+KL partials), 1024-3071 X
    conv_kernel<<<3072, 256>>>(x, wmu, wsg, ew);
    biaskl_kernel<<<1, 1024>>>(bmu, bsg, eb, out, out_size - 1);

    // Persistent 4-CTA-cluster GEMM: 128 CTAs = 32 clusters of 4
    cudaLaunchConfig_t cfg = {};
    cfg.gridDim = dim3(128, 1, 1);
    cfg.blockDim = dim3(GEMM_THREADS, 1, 1);
    cfg.dynamicSmemBytes = GEMM_SMEM;
    cfg.stream = 0;
    cudaLaunchAttribute attrs[1];
    attrs[0].id = cudaLaunchAttributeClusterDimension;
    attrs[0].val.clusterDim.x = 4;
    attrs[0].val.clusterDim.y = 1;
    attrs[0].val.clusterDim.z = 1;
    cfg.attrs = attrs;
    cfg.numAttrs = 1;
    cudaLaunchKernelEx(&cfg, gemm_kernel, out);
}

// round 16
// speedup vs baseline: 1.1858x; 1.0089x over previous
#include <cuda_runtime.h>
#include <cuda_fp16.h>
#include <cstdint>

#define B_DIM   8192
#define IN_DIM  4096
#define OUT_DIM 4096

// ---------------- scratch (static device globals: allocation-free) ----------
// Tiled layout: 16KB blocks = (256 rows x 32 cols) of halves, 64B rows, SW64.
// block index = (row>>8)*KBLK + (col>>5); within: SWZ64((row&255)*64 + (col&31)*2)
// rows 0-127 of a block = first 8KB, rows 128-255 = second 8KB.
__device__ __align__(1024) __half g_xh[(size_t)B_DIM * IN_DIM];     // 64 MB
__device__ __align__(1024) __half g_wh[(size_t)OUT_DIM * IN_DIM];   // 32 MB
__device__ float g_bias[OUT_DIM];
__device__ float g_partial[1024];

// ---------------- common helpers --------------------------------------------
__device__ __forceinline__ uint32_t smem_u32(const void* p) {
    return (uint32_t)__cvta_generic_to_shared(p);
}
#define SWZ64(o) ((o) ^ (((o) >> 3) & 0x30))

// ---------------- GEMM tiling ------------------------------------------------
// 32 clusters of 4 CTAs (128 CTAs). Cluster = two cg2 pairs {0,1},{2,3}, one
// 256(M)x512(N) tile; pair p owns cols ni*512+p*256. A halves multicast {r,r+2}.
// Stage = TK=64: A sub-chunks (8KB+8KB) + B sub-chunks (8KB+8KB) = 32KB.
// 6-stage ring. Leader FULL barrier counts BOTH local expect_tx AND the
// partner forwarder's arrive -> single wait on the MMA critical path.
// D double-buffered in TMEM (slots 0/256).
#define STAGES 6
#define KSTEPS 64                       // IN_DIM / 64
#define A_ST 8192                       // one 128-row x 32-col sub-chunk
#define STAGE_BYTES 32768               // A0,A1,B0,B1
#define OFF_A0 0
#define OFF_A1 8192
#define OFF_B0 16384
#define OFF_B1 24576
#define TILE_BYTES 16384                // one gmem conv block (256 rows x 32 cols)
#define KBLK 128                        // 16KB k-blocks per 256-row band
#define NUM_MT 32
#define NUM_NT 8
#define NUM_PT (NUM_MT * NUM_NT)        // 256 tiles
#define NUM_CLUSTERS 32
#define NTILES (NUM_PT / NUM_CLUSTERS)  // 8 per cluster, exact
#define SM_TMEMPTR 0
#define SM_FULL 16
#define SM_EMPTY (SM_FULL + STAGES * 8)          // 64
#define SM_DONE (SM_EMPTY + STAGES * 8)          // 112
#define SM_TFREE (SM_DONE + 8)                   // 120 (2 slots x 8B)
#define SM_DATA 1024
#define GEMM_SMEM (SM_DATA + STAGES * STAGE_BYTES)  // 197632
#define GEMM_THREADS 320   // warps 0-7 epilogue, warp 8 MMA/fwd, warp 9 producer

// ============================================================================
// Arch-feature-gated tcgen05/cluster helpers (only for sm_10Xa targets)
// ============================================================================
#if defined(__CUDA_ARCH_FEAT_SM103_ALL) || defined(__CUDA_ARCH_FEAT_SM100_ALL) || defined(__CUDA_ARCH_FEAT_SM110_ALL)
#define HAS_TCGEN05 1

__device__ __forceinline__ uint32_t elect_one_pred() {
    uint32_t pred;
    asm volatile("{\n\t.reg .pred p;\n\telect.sync _|p, 0xFFFFFFFF;\n\t"
                 "selp.b32 %0, 1, 0, p;\n\t}" : "=r"(pred));
    return pred;
}
__device__ __forceinline__ uint32_t cluster_rank() {
    uint32_t r;
    asm("mov.u32 %0, %%cluster_ctarank;" : "=r"(r));
    return r;
}
#define CLUSTER_SYNC() do { \
    asm volatile("barrier.cluster.arrive.aligned;" ::: "memory"); \
    asm volatile("barrier.cluster.wait.aligned;" ::: "memory"); \
} while (0)

#define MBARRIER_INIT(addr, count) \
    asm volatile("mbarrier.init.shared.b64 [%0], %1;" :: "r"((uint32_t)(addr)), "r"((uint32_t)(count)) : "memory")
#define MBARRIER_ARRIVE(addr) \
    asm volatile("mbarrier.arrive.shared.b64 _, [%0];" :: "r"((uint32_t)(addr)) : "memory")
#define MBARRIER_ARRIVE_CLUSTER(local_addr, target_rank) \
    asm volatile("{\n\t.reg .b32 remAddr;\n\t" \
        "mapa.shared::cluster.u32 remAddr, %0, %1;\n\t" \
        "mbarrier.arrive.shared::cluster.b64 _, [remAddr];\n\t}" \
        :: "r"((uint32_t)(local_addr)), "r"((uint32_t)(target_rank)) : "memory")
#define MBARRIER_EXPECT_TX(addr, bytes) \
    asm volatile("mbarrier.arrive.expect_tx.shared.b64 _, [%0], %1;" :: "r"((uint32_t)(addr)), "r"((uint32_t)(bytes)) : "memory")
#define MBARRIER_WAIT_PARITY(mbar_smem_addr, phase_parity) do { \
    uint32_t _mbar = (uint32_t)(mbar_smem_addr); \
    uint32_t _parity = (uint32_t)(phase_parity); \
    uint32_t _done; \
    asm volatile("{\n\t.reg .pred p;\n\t" \
        "mbarrier.try_wait.parity.acquire.cta.shared::cta.b64 p, [%1], %2;\n\t" \
        "selp.b32 %0, 1, 0, p;\n\t}" : "=r"(_done) : "r"(_mbar), "r"(_parity) : "memory"); \
    if (!_done) { \
        asm volatile("{\n\t.reg .pred P1;\n\t" \
            "WAIT_LOOP_%=:\n\t" \
            "mbarrier.try_wait.parity.acquire.cta.shared::cta.b64 P1, [%0], %1, 0x989680;\n\t" \
            "@P1 bra.uni WAIT_DONE_%=;\n\t" \
            "bra.uni WAIT_LOOP_%=;\n\t" \
            "WAIT_DONE_%=:\n\t}" :: "r"(_mbar), "r"(_parity) : "memory"); \
    } \
} while (0)

#define BULK_G2S(dst, src, bytes, mbar) \
    asm volatile("cp.async.bulk.shared::cta.global.mbarrier::complete_tx::bytes [%0], [%1], %2, [%3];" \
        :: "r"((uint32_t)(dst)), "l"(src), "r"((uint32_t)(bytes)), "r"((uint32_t)(mbar)) : "memory")
#define BULK_G2S_MC(dst, src, bytes, mbar, mask) \
    asm volatile("cp.async.bulk.shared::cluster.global.mbarrier::complete_tx::bytes.multicast::cluster [%0], [%1], %2, [%3], %4;" \
        :: "r"((uint32_t)(dst)), "l"(src), "r"((uint32_t)(bytes)), "r"((uint32_t)(mbar)), "h"((uint16_t)(mask)) : "memory")

#define TCGEN05_ALLOC_CG2(smem_result_addr, nCols) \
    asm volatile("tcgen05.alloc.cta_group::2.sync.aligned.shared::cta.b32 [%0], %1;" \
        :: "r"((uint32_t)(smem_result_addr)), "r"((uint32_t)(nCols)) : "memory")
#define TCGEN05_DEALLOC_CG2(tmem_addr, nCols) \
    asm volatile("tcgen05.dealloc.cta_group::2.sync.aligned.b32 %0, %1;" :: "r"(tmem_addr), "r"((uint32_t)(nCols)))
#define TCGEN05_RELINQUISH_CG2() \
    asm volatile("tcgen05.relinquish_alloc_permit.cta_group::2.sync.aligned;")
#define TCGEN05_COMMIT_MC_CG2(mbar, mask) \
    asm volatile("tcgen05.commit.cta_group::2.mbarrier::arrive::one.shared::cluster.multicast::cluster.b64 [%0], %1;" \
        :: "r"((uint32_t)(mbar)), "h"((uint16_t)(mask)) : "memory")
#define TCGEN05_FENCE_AFTER()  asm volatile("tcgen05.fence::after_thread_sync;" ::: "memory")
#define TCGEN05_FENCE_BEFORE() asm volatile("tcgen05.fence::before_thread_sync;" ::: "memory")
#define TCGEN05_WAIT_LD()      asm volatile("tcgen05.wait::ld.sync.aligned;" ::: "memory")
#define FENCE_PROXY_ASYNC()    asm volatile("fence.proxy.async.shared::cta;" ::: "memory")

#define TCGEN05_LD_32X32B_X32(r, tmem_addr) \
    asm volatile("tcgen05.ld.sync.aligned.32x32b.x32.b32 " \
        "{%0, %1, %2, %3, %4, %5, %6, %7, " \
        " %8, %9, %10, %11, %12, %13, %14, %15, " \
        " %16, %17, %18, %19, %20, %21, %22, %23, " \
        " %24, %25, %26, %27, %28, %29, %30, %31}, [%32];" \
        : "=r"((r)[0]),  "=r"((r)[1]),  "=r"((r)[2]),  "=r"((r)[3]), \
          "=r"((r)[4]),  "=r"((r)[5]),  "=r"((r)[6]),  "=r"((r)[7]), \
          "=r"((r)[8]),  "=r"((r)[9]),  "=r"((r)[10]), "=r"((r)[11]), \
          "=r"((r)[12]), "=r"((r)[13]), "=r"((r)[14]), "=r"((r)[15]), \
          "=r"((r)[16]), "=r"((r)[17]), "=r"((r)[18]), "=r"((r)[19]), \
          "=r"((r)[20]), "=r"((r)[21]), "=r"((r)[22]), "=r"((r)[23]), \
          "=r"((r)[24]), "=r"((r)[25]), "=r"((r)[26]), "=r"((r)[27]), \
          "=r"((r)[28]), "=r"((r)[29]), "=r"((r)[30]), "=r"((r)[31]) \
        : "r"(tmem_addr))

// cg2 f16 SS MMA: M=256 across the pair, 8 disable-lane regs (all zero).
__device__ __forceinline__ void mma_f16_ss_cg2(uint32_t d, uint64_t a_desc, uint64_t b_desc,
                                               uint32_t idesc, uint32_t enable) {
    asm volatile("{\n\t.reg .pred p;\n\tsetp.ne.u32 p, %5, 0;\n\t"
        "tcgen05.mma.cta_group::2.kind::f16 [%0], %1, %2, %3, "
        "{%4, %4, %4, %4, %4, %4, %4, %4}, p;\n\t}"
        :: "r"(d), "l"(a_desc), "l"(b_desc), "r"(idesc), "r"(0u), "r"(enable) : "memory");
}
// SW64 K-major descriptor: layout=4, version=1, SBO=32 (512B per 8-row atom), LBO=1
__device__ __forceinline__ uint64_t make_desc64(uint32_t addr) {
    const uint64_t base = (4ULL << 61) | (1ULL << 46) | (32ULL << 32) | (1ULL << 16);
    return base | ((uint64_t)(addr >> 4) & 0x3FFF);
}
// F32 acc (1<<4), f16 inputs, N=256 (bits[17:22]=N>>3), M=256 (bits[24:28]=M>>4)
#define IDESC_CG2 ((1u << 4) | (32u << 17) | (16u << 24))
#endif  // arch feature

// ---------------- kernel 1: fused conversions --------------------------------
// blocks 0-1023:    W -> fp16 tiled SW64 + KL partials (16384 elems/block)
// blocks 1024-3071: X -> fp16 tiled SW64 (16384 elems/block)
__global__ void __launch_bounds__(256) conv_kernel(const float* __restrict__ x,
                                                   const float* __restrict__ mu,
                                                   const float* __restrict__ sg,
                                                   const float* __restrict__ ep) {
    int t = threadIdx.x;
    if (blockIdx.x < 1024) {
        __shared__ float red[256];
        size_t b4 = (size_t)blockIdx.x * 4096;  // float4 index base
        float acc = 0.f;
#pragma unroll
        for (int i = 0; i < 16; i++) {
            size_t idx = b4 + (size_t)i * 256 + t;       // float4 index
            float4 m = ((const float4*)mu)[idx];
            float4 s = ((const float4*)sg)[idx];
            float4 e = ((const float4*)ep)[idx];
            float e0 = __expf(s.x), e1 = __expf(s.y), e2 = __expf(s.z), e3 = __expf(s.w);
            float w0 = m.x + e0 * e.x, w1 = m.y + e1 * e.y;
            float w2 = m.z + e2 * e.z, w3 = m.w + e3 * e.w;
            __half2 h01 = __floats2half2_rn(w0, w1);
            __half2 h23 = __floats2half2_rn(w2, w3);
            uint2 pk;
            pk.x = *reinterpret_cast<uint32_t*>(&h01);
            pk.y = *reinterpret_cast<uint32_t*>(&h23);
            int r = (int)(idx >> 10);                    // row (1024 float4/row)
            int c = ((int)idx & 1023) * 4;               // col in halves
            size_t blk = (size_t)((r >> 8) * KBLK + (c >> 5));
            uint32_t off = (uint32_t)((r & 255) * 64 + (c & 31) * 2);
            *reinterpret_cast<uint2*>((char*)g_wh + blk * TILE_BYTES + SWZ64(off)) = pk;
            acc += 4.f + 2.f * (s.x + s.y + s.z + s.w)
                       - (m.x * m.x + m.y * m.y + m.z * m.z + m.w * m.w)
                       - (e0 * e0 + e1 * e1 + e2 * e2 + e3 * e3);
        }
        red[t] = acc;
        __syncthreads();
        for (int o = 128; o > 0; o >>= 1) {
            if (t < o) red[t] += red[t + o];
            __syncthreads();
        }
        if (t == 0) g_partial[blockIdx.x] = red[0];
    } else {
        size_t b4 = (size_t)(blockIdx.x - 1024) * 4096;
#pragma unroll
        for (int i = 0; i < 16; i++) {
            size_t idx = b4 + (size_t)i * 256 + t;
            float4 v = ((const float4*)x)[idx];
            __half2 h01 = __floats2half2_rn(v.x, v.y);
            __half2 h23 = __floats2half2_rn(v.z, v.w);
            uint2 pk;
            pk.x = *reinterpret_cast<uint32_t*>(&h01);
            pk.y = *reinterpret_cast<uint32_t*>(&h23);
            int r = (int)(idx >> 10);
            int c = ((int)idx & 1023) * 4;
            size_t blk = (size_t)((r >> 8) * KBLK + (c >> 5));
            uint32_t off = (uint32_t)((r & 255) * 64 + (c & 31) * 2);
            *reinterpret_cast<uint2*>((char*)g_xh + blk * TILE_BYTES + SWZ64(off)) = pk;
        }
    }
}

// ---------------- kernel 2: bias + final KL ---------------------------------
__global__ void __launch_bounds__(1024) biaskl_kernel(const float* __restrict__ bmu,
                                                      const float* __restrict__ bsg,
                                                      const float* __restrict__ beb,
                                                      float* __restrict__ out, int klidx) {
    __shared__ float red[1024];
    int t = threadIdx.x;
    float acc = 0.f;
    for (int i = t; i < OUT_DIM; i += 1024) {
        float m = bmu[i], s = bsg[i], e = beb[i];
        float es = __expf(s);
        g_bias[i] = m + es * e;
        acc += 1.f + 2.f * s - m * m - es * es;
    }
    acc += g_partial[t];
    red[t] = acc;
    __syncthreads();
    for (int o = 512; o > 0; o >>= 1) {
        if (t < o) red[t] += red[t + o];
        __syncthreads();
    }
    if (t == 0) out[klidx] = -0.5f * red[0];
}

// ---------------- kernel 3: persistent 4-CTA cg2 GEMM, 256x512 tiles ---------
// rank r: p=r>>1 (pair), h=r&1 (half). A half h loaded by ranks 0/1, multicast
// to {h, h+2}. B band (ni*2+p) half h local. Pair leaders (ranks 0,2): FULL
// counts local expect_tx + partner forwarder arrive -> ONE wait per stage on
// the MMA critical path. Forwarders (1,3) relay into leader's FULL.
__global__ void __launch_bounds__(GEMM_THREADS, 1) gemm_kernel(float* __restrict__ out) {
    extern __shared__ __align__(1024) char smem[];
    uint32_t sb = smem_u32(smem);
    int tid = threadIdx.x;
    int wid = tid >> 5;
    int lid = tid & 31;

#if defined(HAS_TCGEN05)
    uint32_t rank = cluster_rank();
    int p = (int)(rank >> 1);
    int h = (int)(rank & 1);
    int cid = blockIdx.x >> 2;
    int mi = cid;                       // pt = cid + 32w -> mi = cid, ni = w

    if (tid == 0) {
        uint32_t full_cnt = (h == 0) ? 2u : 1u;   // leader: +partner forwarder arrive
        for (int s = 0; s < STAGES; s++) {
            MBARRIER_INIT(sb + SM_FULL + s * 8, full_cnt);
            MBARRIER_INIT(sb + SM_EMPTY + s * 8, 2);     // both leaders' commits
        }
        MBARRIER_INIT(sb + SM_DONE, 1);                  // own pair's commit per tile
        MBARRIER_INIT(sb + SM_TFREE, 16);                // slot0: 8 warps x 2 CTAs (pair)
        MBARRIER_INIT(sb + SM_TFREE + 8, 16);            // slot1
        FENCE_PROXY_ASYNC();
        for (int s = 0; s < STAGES; s++) {               // pre-arm empty phase 0 (count=2)
            MBARRIER_ARRIVE(sb + SM_EMPTY + s * 8);
            MBARRIER_ARRIVE(sb + SM_EMPTY + s * 8);
        }
        for (int i = 0; i < 16; i++) {                   // pre-arm both tfree slots
            MBARRIER_ARRIVE(sb + SM_TFREE);
            MBARRIER_ARRIVE(sb + SM_TFREE + 8);
        }
    }
    if (wid == 8) TCGEN05_ALLOC_CG2(sb + SM_TMEMPTR, 512);
    __syncthreads();
    CLUSTER_SYNC();   // cluster-wide barrier/TMEM init before any cross-CTA traffic
    uint32_t tmem;
    asm volatile("ld.shared.b32 %0, [%1];" : "=r"(tmem) : "r"(sb + SM_TMEMPTR));

    if (wid == 9 && lid == 0) {
        // ---- producer: ranks 0/1 multicast A half h to {h,h+2}; all load own B ----
        const char* srcA = (const char*)g_xh + (size_t)mi * KBLK * TILE_BYTES + h * A_ST;
        uint16_t maskA = (uint16_t)(0x5u << h);          // {h, h+2}
        int s = 0, ph = 0;
        for (int w = 0; w < NTILES; w++) {
            int ni = w;
            const char* srcB = (const char*)g_wh + (size_t)(ni * 2 + p) * KBLK * TILE_BYTES + h * A_ST;
            for (int ks = 0; ks < KSTEPS; ks++) {
                MBARRIER_WAIT_PARITY(sb + SM_EMPTY + s * 8, ph);
                uint32_t stage_base = sb + SM_DATA + s * STAGE_BYTES;
                size_t g0 = (size_t)(ks * 2) * TILE_BYTES;
                size_t g1 = (size_t)(ks * 2 + 1) * TILE_BYTES;
                MBARRIER_EXPECT_TX(sb + SM_FULL + s * 8, STAGE_BYTES);
                if (p == 0) {
                    BULK_G2S_MC(stage_base + OFF_A0, srcA + g0, A_ST, sb + SM_FULL + s * 8, maskA);
                    BULK_G2S_MC(stage_base + OFF_A1, srcA + g1, A_ST, sb + SM_FULL + s * 8, maskA);
                }
                BULK_G2S(stage_base + OFF_B0, srcB + g0, A_ST, sb + SM_FULL + s * 8);
                BULK_G2S(stage_base + OFF_B1, srcB + g1, A_ST, sb + SM_FULL + s * 8);
                if (++s == STAGES) { s = 0; ph ^= 1; }
            }
        }
    }
    if (wid == 8) {
        int s = 0, ph = 0;
        if (h == 1) {
            // ---- forwarder (ranks 1,3): relay local stage-full into leader's FULL ----
            int total = NTILES * KSTEPS;
            int target = p * 2;
            for (int i = 0; i < total; i++) {
                MBARRIER_WAIT_PARITY(sb + SM_FULL + s * 8, ph);
                if (elect_one_pred()) MBARRIER_ARRIVE_CLUSTER(sb + SM_FULL + s * 8, target);
                if (++s == STAGES) { s = 0; ph ^= 1; }
            }
        } else {
            // ---- pair leader (ranks 0,2): ONE wait + 4 cg2 dispatches per stage ----
            uint16_t done_mask = (p == 0) ? 0x3 : 0xC;
            for (int w = 0; w < NTILES; w++) {
                MBARRIER_WAIT_PARITY(sb + SM_TFREE + (w & 1) * 8, (w >> 1) & 1);  // D slot free
                uint32_t dslot = tmem + (w & 1) * 256;
                for (int ks = 0; ks < KSTEPS; ks++) {
                    MBARRIER_WAIT_PARITY(sb + SM_FULL + s * 8, ph);  // both halves ready
                    if (elect_one_pred()) {
                        uint32_t stage_base = sb + SM_DATA + s * STAGE_BYTES;
                        uint64_t a0 = make_desc64(stage_base + OFF_A0);
                        uint64_t a1 = make_desc64(stage_base + OFF_A1);
                        uint64_t b0 = make_desc64(stage_base + OFF_B0);
                        uint64_t b1 = make_desc64(stage_base + OFF_B1);
                        uint32_t en = (ks == 0) ? 0u : 1u;
                        mma_f16_ss_cg2(dslot, a0,     b0,     IDESC_CG2, en);
                        mma_f16_ss_cg2(dslot, a0 + 2, b0 + 2, IDESC_CG2, 1u);
                        mma_f16_ss_cg2(dslot, a1,     b1,     IDESC_CG2, 1u);
                        mma_f16_ss_cg2(dslot, a1 + 2, b1 + 2, IDESC_CG2, 1u);
                        TCGEN05_COMMIT_MC_CG2(sb + SM_EMPTY + s * 8, 0xF);  // free stage: all 4 CTAs
                    }
                    if (++s == STAGES) { s = 0; ph ^= 1; }
                }
                if (elect_one_pred()) TCGEN05_COMMIT_MC_CG2(sb + SM_DONE, done_mask);
            }
        }
    }
    if (wid < 8) {
        // ---- epilogue warps: drain own 128 rows x 256 cols (pair's N-half) ----
        int chalf = wid >> 2;         // column half within pair (0-127 / 128-255)
        int w4 = wid & 3;             // TMEM subpartition (lanes w4*32..+31)
        int tfree_target = p * 2;
        for (int w = 0; w < NTILES; w++) {
            int ni = w;
            int row = mi * 256 + h * 128 + w4 * 32 + lid;
            int n0 = ni * 512 + p * 256 + chalf * 128;
            float* orow = out + (size_t)row * OUT_DIM + n0;
            uint32_t tbase = tmem + (w & 1) * 256 + chalf * 128;
            MBARRIER_WAIT_PARITY(sb + SM_DONE, w & 1);
            TCGEN05_FENCE_AFTER();
#pragma unroll 1
            for (int cc = 0; cc < 4; cc++) {
                uint32_t r[32];
                TCGEN05_LD_32X32B_X32(r, tbase + cc * 32);
                TCGEN05_WAIT_LD();
                const float4* bv4 = (const float4*)(g_bias + n0 + cc * 32);
                float4* o4 = (float4*)(orow + cc * 32);
#pragma unroll
                for (int j = 0; j < 8; j++) {
                    float4 bv = bv4[j];
                    float4 v;
                    v.x = __uint_as_float(r[j * 4 + 0]) + bv.x;
                    v.y = __uint_as_float(r[j * 4 + 1]) + bv.y;
                    v.z = __uint_as_float(r[j * 4 + 2]) + bv.z;
                    v.w = __uint_as_float(r[j * 4 + 3]) + bv.w;
                    o4[j] = v;
                }
            }
            TCGEN05_FENCE_BEFORE();
            if (lid == 0) MBARRIER_ARRIVE_CLUSTER(sb + SM_TFREE + (w & 1) * 8, tfree_target);
        }
    }

    __syncthreads();
    CLUSTER_SYNC();   // all consumption of peer SMEM/TMEM done cluster-wide
    if (wid == 8) {
        TCGEN05_RELINQUISH_CG2();
        TCGEN05_DEALLOC_CG2(tmem, 512);
    }
    CLUSTER_SYNC();
#else
    // ============== correctness-only fallback (never executes on sm_103a) ====
    uint32_t rank = blockIdx.x & 3;
    int p = (int)(rank >> 1), h = (int)(rank & 1);
    int cid = blockIdx.x >> 2;
    int mi = cid;
    for (int w = 0; w < NTILES; w++) {
        int ni = w;
        for (int idx = tid; idx < 128 * 256; idx += GEMM_THREADS) {
            int r = mi * 256 + h * 128 + (idx >> 8);
            int c = ni * 512 + p * 256 + (idx & 255);
            float acc = 0.f;
            for (int k = 0; k < IN_DIM; k++) {
                size_t xblk = (size_t)((r >> 8) * KBLK + (k >> 5));
                uint32_t xoff = SWZ64((uint32_t)((r & 255) * 64 + (k & 31) * 2));
                size_t wblk = (size_t)((c >> 8) * KBLK + (k >> 5));
                uint32_t woff = SWZ64((uint32_t)((c & 255) * 64 + (k & 31) * 2));
                float xv = __half2float(*(const __half*)((const char*)g_xh + xblk * TILE_BYTES + xoff));
                float wv = __half2float(*(const __half*)((const char*)g_wh + wblk * TILE_BYTES + woff));
                acc += xv * wv;
            }
            out[(size_t)r * OUT_DIM + c] = acc + g_bias[c];
        }
    }
#endif
}

// ---------------- launch -----------------------------------------------------
extern "C" void kernel_launch(void* const* d_in, const int* in_sizes, int n_in,
                              void* d_out, int out_size) {
    const float* x   = (const float*)d_in[0];
    const float* wmu = (const float*)d_in[1];
    const float* wsg = (const float*)d_in[2];
    const float* bmu = (const float*)d_in[3];
    const float* bsg = (const float*)d_in[4];
    const float* ew  = (const float*)d_in[5];
    const float* eb  = (const float*)d_in[6];
    float* out = (float*)d_out;

    cudaFuncSetAttribute(gemm_kernel, cudaFuncAttributeMaxDynamicSharedMemorySize, GEMM_SMEM);

    // Fused conversions: blocks 0-1023 W (+KL partials), 1024-3071 X
    conv_kernel<<<3072, 256>>>(x, wmu, wsg, ew);
    biaskl_kernel<<<1, 1024>>>(bmu, bsg, eb, out, out_size - 1);

    // Persistent 4-CTA-cluster GEMM: 128 CTAs = 32 clusters of 4
    cudaLaunchConfig_t cfg = {};
    cfg.gridDim = dim3(128, 1, 1);
    cfg.blockDim = dim3(GEMM_THREADS, 1, 1);
    cfg.dynamicSmemBytes = GEMM_SMEM;
    cfg.stream = 0;
    cudaLaunchAttribute attrs[1];
    attrs[0].id = cudaLaunchAttributeClusterDimension;
    attrs[0].val.clusterDim.x = 4;
    attrs[0].val.clusterDim.y = 1;
    attrs[0].val.clusterDim.z = 1;
    cfg.attrs = attrs;
    cfg.numAttrs = 1;
    cudaLaunchKernelEx(&cfg, gemm_kernel, out);
}